// round 13
// baseline (speedup 1.0000x reference)
#include <cuda_runtime.h>
#include <cuda_fp16.h>
#include <cstdint>
#include <math.h>

// Problem constants
#define BATCH   4
#define SEQ     2048
#define DMODEL  1024
#define NHEADS  16
#define HDIM    64
#define MTOT    (BATCH * SEQ)          // 8192 rows

// ---------------------------------------------------------------------------
// Scratch (static __device__ — no allocations allowed)
// ---------------------------------------------------------------------------
__device__ __half g_xh[MTOT * DMODEL];
__device__ __half g_qh[MTOT * DMODEL];
__device__ __half g_kh[MTOT * DMODEL];
__device__ __half g_vth[MTOT * DMODEL];   // [b*16+h][64 dims][2048 T]
__device__ __half g_ath[MTOT * DMODEL];
__device__ __half g_wh[4][DMODEL * DMODEL];
__device__ __half g_wl[4][DMODEL * DMODEL];

// ---------------------------------------------------------------------------
// mma.sync / ldmatrix / cp.async helpers (portable PTX, valid on plain sm_103)
// ---------------------------------------------------------------------------
__device__ __forceinline__ uint32_t smem_to_u32(const void* p) {
    uint32_t a;
    asm("{ .reg .u64 t; cvta.to.shared.u64 t, %1; cvt.u32.u64 %0, t; }" : "=r"(a) : "l"(p));
    return a;
}
__device__ __forceinline__ void ldsm4(uint32_t* d, uint32_t addr) {
    asm volatile("ldmatrix.sync.aligned.m8n8.x4.shared.b16 {%0,%1,%2,%3}, [%4];"
                 : "=r"(d[0]), "=r"(d[1]), "=r"(d[2]), "=r"(d[3]) : "r"(addr));
}
__device__ __forceinline__ void mma16816(float* c, const uint32_t* a, const uint32_t* b) {
    asm volatile("mma.sync.aligned.m16n8k16.row.col.f32.f16.f16.f32 "
                 "{%0,%1,%2,%3}, {%4,%5,%6,%7}, {%8,%9}, {%0,%1,%2,%3};"
                 : "+f"(c[0]), "+f"(c[1]), "+f"(c[2]), "+f"(c[3])
                 : "r"(a[0]), "r"(a[1]), "r"(a[2]), "r"(a[3]), "r"(b[0]), "r"(b[1]));
}
__device__ __forceinline__ uint32_t pack_h2(float a, float b) {
    __half2 t = __floats2half2_rn(a, b);
    return *reinterpret_cast<uint32_t*>(&t);
}
#define CP_ASYNC16(dst, src) \
    asm volatile("cp.async.cg.shared.global [%0], [%1], 16;" \
                 :: "r"(dst), "l"(__cvta_generic_to_global(src)) : "memory")
#define CP_COMMIT() asm volatile("cp.async.commit_group;" ::: "memory")
#define CP_WAIT(n)  asm volatile("cp.async.wait_group %0;" :: "n"(n) : "memory")

// SW128-style swizzle for 128B rows (all tiles)
#define SWZ128(o) ((o) ^ (((o) >> 3) & 0x70))

// scale (1/sqrt(64)) * log2(e) — folded into K at projection time
#define K_FOLD 0.18033688011112042f

// ---------------------------------------------------------------------------
// fp16 splits
// ---------------------------------------------------------------------------
__global__ void split_h(const float* __restrict__ in, __half* __restrict__ hi, int n4)
{
    int i = blockIdx.x * blockDim.x + threadIdx.x;
    if (i >= n4) return;
    float4 x = ((const float4*)in)[i];
    ((__half2*)hi)[i * 2 + 0] = __floats2half2_rn(x.x, x.y);
    ((__half2*)hi)[i * 2 + 1] = __floats2half2_rn(x.z, x.w);
}

__global__ void split_w4(const float* __restrict__ w0, const float* __restrict__ w1,
                         const float* __restrict__ w2, const float* __restrict__ w3,
                         __half* __restrict__ hi, __half* __restrict__ lo)
{
    const int n4 = DMODEL * DMODEL / 4;
    int i = blockIdx.x * blockDim.x + threadIdx.x;
    if (i >= n4) return;
    int z = blockIdx.y;
    const float* src = (z == 0) ? w0 : (z == 1) ? w1 : (z == 2) ? w2 : w3;
    size_t base = (size_t)z * (DMODEL * DMODEL / 2);   // in __half2 units
    float4 x = ((const float4*)src)[i];
    __half2 h0 = __floats2half2_rn(x.x, x.y);
    __half2 h1 = __floats2half2_rn(x.z, x.w);
    ((__half2*)hi)[base + i * 2 + 0] = h0;
    ((__half2*)hi)[base + i * 2 + 1] = h1;
    __half2 l0 = __floats2half2_rn(x.x - __half2float(h0.x), x.y - __half2float(h0.y));
    __half2 l1 = __floats2half2_rn(x.z - __half2float(h1.x), x.w - __half2float(h1.y));
    ((__half2*)lo)[base + i * 2 + 0] = l0;
    ((__half2*)lo)[base + i * 2 + 1] = l1;
}

// ---------------------------------------------------------------------------
// HMMA fp16 2-pass GEMM, BK=64. SW128 tiles throughout.
// ---------------------------------------------------------------------------
#define BK 64
#define NCHUNK (DMODEL / BK)           // 16
#define TILE_BYTES (128 * 128)         // 16 KB
#define STAGE_BYTES (3 * TILE_BYTES)   // 48 KB
#define GEMM_SMEM (2 * STAGE_BYTES)    // 96 KB

struct GemmArgs {
    const __half* Ah;
    const __half* Bh;
    const __half* Bl;
    const float*  bias;
    float*        Cf;
    __half*       Ch;
    __half*       Cl;
    int           mode;     // 0 fp32; 1 hi/lo rows; 2 [b,h,d,T] (lo iff Cl); 3 hi rows
    float         cscale;   // output scale (K fold); 1.0 otherwise
};
struct GemmArgs3 { GemmArgs g[3]; };

__global__ __launch_bounds__(256, 2)
void gemm_hmma2(GemmArgs3 A3)
{
    const GemmArgs ga = A3.g[blockIdx.z];
    extern __shared__ __align__(16) char smem[];
    const uint32_t smem_u = smem_to_u32(smem);

    const int tid  = threadIdx.x;
    const int wid  = tid >> 5;
    const int lane = tid & 31;
    const int wm   = wid & 1;
    const int wn   = wid >> 1;
    const int m0 = blockIdx.y * 128;
    const int n0 = blockIdx.x * 128;

    const uint32_t mS = (uint32_t)(lane & 7) << 4;
    const int rowA_l = (lane & 7) + ((lane >> 3) & 1) * 8;
    const int chiA   = (lane >> 4) & 1;
    const int rbB_l  = (lane & 7) + ((lane >> 4) & 1) * 8;
    const int chiB   = (lane >> 3) & 1;
    const uint32_t rowbaseA = (uint32_t)(wm * 64 + rowA_l) * 128;
    const uint32_t rowbaseB = (uint32_t)(wn * 32 + rbB_l) * 128;
    uint32_t colA[4], colB[4];
#pragma unroll
    for (int kt = 0; kt < 4; kt++) {
        colA[kt] = ((uint32_t)((kt * 2 + chiA) * 16)) ^ mS;
        colB[kt] = ((uint32_t)((kt * 2 + chiB) * 16)) ^ mS;
    }

    float acc[4][4][4];
#pragma unroll
    for (int mt = 0; mt < 4; mt++)
#pragma unroll
        for (int nt = 0; nt < 4; nt++)
#pragma unroll
            for (int e = 0; e < 4; e++) acc[mt][nt][e] = 0.f;

    const __half* srcs[3] = { ga.Ah, ga.Bh, ga.Bl };

    auto cpa = [&](int c, int s) {
        const int k0 = c * BK;
        const uint32_t st = smem_u + s * STAGE_BYTES;
#pragma unroll
        for (int t = 0; t < 3; t++) {
            const __half* src = srcs[t];
            const int r0 = (t == 0) ? m0 : n0;
#pragma unroll
            for (int i = 0; i < 4; i++) {
                int fid = tid + i * 256;
                int row = fid >> 3, cc = fid & 7;
                uint32_t dst = st + t * TILE_BYTES + SWZ128(row * 128 + cc * 16);
                CP_ASYNC16(dst, src + (size_t)(r0 + row) * DMODEL + k0 + cc * 8);
            }
        }
    };

    auto mma_chunk = [&](int s) {
        const uint32_t sb = smem_u + s * STAGE_BYTES;
#pragma unroll
        for (int kt = 0; kt < 4; kt++) {
            uint32_t a[4][4];
#pragma unroll
            for (int mt = 0; mt < 4; mt++)
                ldsm4(a[mt], sb + rowbaseA + mt * 2048 + colA[kt]);
#pragma unroll
            for (int np = 0; np < 2; np++) {
                uint32_t bh[4], bl[4];
                ldsm4(bh, sb + TILE_BYTES + rowbaseB + np * 2048 + colB[kt]);
                ldsm4(bl, sb + 2 * TILE_BYTES + rowbaseB + np * 2048 + colB[kt]);
#pragma unroll
                for (int mt = 0; mt < 4; mt++) {
                    mma16816(acc[mt][2 * np + 0], a[mt], &bh[0]);
                    mma16816(acc[mt][2 * np + 1], a[mt], &bh[2]);
                    mma16816(acc[mt][2 * np + 0], a[mt], &bl[0]);
                    mma16816(acc[mt][2 * np + 1], a[mt], &bl[2]);
                }
            }
        }
    };

    cpa(0, 0); CP_COMMIT();
    for (int c = 0; c < NCHUNK; c++) {
        if (c + 1 < NCHUNK) {
            cpa(c + 1, (c + 1) & 1); CP_COMMIT();
            CP_WAIT(1);
        } else {
            CP_WAIT(0);
        }
        __syncthreads();
        mma_chunk(c & 1);
        __syncthreads();
    }

    // Epilogue
    const int g  = lane >> 2;
    const int t2 = (lane & 3) * 2;
#pragma unroll
    for (int mt = 0; mt < 4; mt++) {
#pragma unroll
        for (int nt = 0; nt < 4; nt++) {
            int row = m0 + wm * 64 + mt * 16 + g;
            int col = n0 + wn * 32 + nt * 8 + t2;
            float2 b = *(const float2*)&ga.bias[col];
            float v0 = (acc[mt][nt][0] + b.x) * ga.cscale;
            float v1 = (acc[mt][nt][1] + b.y) * ga.cscale;
            float v2 = (acc[mt][nt][2] + b.x) * ga.cscale;
            float v3 = (acc[mt][nt][3] + b.y) * ga.cscale;
            if (ga.mode == 0) {
                float2 o0 = { v0, v1 }, o1 = { v2, v3 };
                *(float2*)&ga.Cf[(size_t)row * DMODEL + col] = o0;
                *(float2*)&ga.Cf[(size_t)(row + 8) * DMODEL + col] = o1;
            } else if (ga.mode == 1) {
                __half2 H0 = __floats2half2_rn(v0, v1);
                __half2 H1 = __floats2half2_rn(v2, v3);
                *(__half2*)(ga.Ch + (size_t)row * DMODEL + col) = H0;
                *(__half2*)(ga.Ch + (size_t)(row + 8) * DMODEL + col) = H1;
                __half2 L0 = __floats2half2_rn(v0 - __half2float(H0.x), v1 - __half2float(H0.y));
                __half2 L1 = __floats2half2_rn(v2 - __half2float(H1.x), v3 - __half2float(H1.y));
                *(__half2*)(ga.Cl + (size_t)row * DMODEL + col) = L0;
                *(__half2*)(ga.Cl + (size_t)(row + 8) * DMODEL + col) = L1;
            } else if (ga.mode == 3) {
                __half2 H0 = __floats2half2_rn(v0, v1);
                __half2 H1 = __floats2half2_rn(v2, v3);
                *(__half2*)(ga.Ch + (size_t)row * DMODEL + col) = H0;
                *(__half2*)(ga.Ch + (size_t)(row + 8) * DMODEL + col) = H1;
            } else {
                // V transposed layout: idx = ((b*16+h)*64 + d)*2048 + t
#pragma unroll
                for (int e = 0; e < 4; e++) {
                    float v = (e == 0) ? v0 : (e == 1) ? v1 : (e == 2) ? v2 : v3;
                    int r = row + (e >= 2 ? 8 : 0);
                    int c = col + (e & 1);
                    int bb = r >> 11, t = r & 2047;
                    int hh = c >> 6, dl = c & 63;
                    size_t idx = ((size_t)((bb * 16 + hh) * 64 + dl)) * 2048 + t;
                    __half hv = __float2half_rn(v);
                    ga.Ch[idx] = hv;
                    if (ga.Cl) ga.Cl[idx] = __float2half_rn(v - __half2float(hv));
                }
            }
        }
    }
}

// ---------------------------------------------------------------------------
// HMMA pure-fp16 causal flash attention (log2-domain softmax).
// S = Qh·Kh (K carries scale*log2e) ; O = Ph·Vh ; fp32 accumulation.
// K/V hi-only double-buffered (2 x 16 KB). 48 KB smem, 2 CTAs/SM.
// ---------------------------------------------------------------------------
#define AQ_B (128 * 128)               // 16 KB Q tile
#define AK_B (64 * 128)                // 8 KB per K/V tile
#define KV_STAGE (2 * AK_B)            // 16 KB
#define ATT_SMEM (AQ_B + 2 * KV_STAGE) // 48 KB

__global__ __launch_bounds__(256, 2)
void attn_hmma(const __half* __restrict__ qh,
               const __half* __restrict__ kh,
               const __half* __restrict__ vth,
               __half* __restrict__ oh)
{
    extern __shared__ __align__(16) char smem[];
    const uint32_t smem_u = smem_to_u32(smem);
    char* sQh = smem;
    const uint32_t uQh = smem_u;
    const uint32_t uKV = uQh + AQ_B;

    const int tid  = threadIdx.x;
    const int wid  = tid >> 5;
    const int lane = tid & 31;
    const int g    = lane >> 2;
    const int t2   = (lane & 3) * 2;

    const int qb = (gridDim.x - 1) - blockIdx.x;   // heavy CTAs first
    const int bh = blockIdx.y;
    const int b  = bh >> 4;
    const int h  = bh & 15;

    const int q0loc  = qb * 128;
    const int rowg   = b * SEQ + q0loc;
    const __half* qhb = qh + (size_t)rowg * DMODEL + h * HDIM;
    const __half* khb = kh + (size_t)(b * SEQ) * DMODEL + h * HDIM;
    const __half* vhb = vth + (size_t)bh * 64 * SEQ;

    const uint32_t mS = (uint32_t)(lane & 7) << 4;
    const int rowA_l = (lane & 7) + ((lane >> 3) & 1) * 8;
    const int chiA   = (lane >> 4) & 1;
    const int rbB_l  = (lane & 7) + ((lane >> 4) & 1) * 8;
    const int chiB   = (lane >> 3) & 1;
    const uint32_t rowbaseA = (uint32_t)(wid * 16 + rowA_l) * 128;
    const uint32_t rowbaseB = (uint32_t)rbB_l * 128;
    uint32_t colA[4], colB[4];
#pragma unroll
    for (int kt = 0; kt < 4; kt++) {
        colA[kt] = ((uint32_t)((kt * 2 + chiA) * 16)) ^ mS;
        colB[kt] = ((uint32_t)((kt * 2 + chiB) * 16)) ^ mS;
    }

    // Load Q tile (hi only)
    for (int it = tid; it < 1024; it += 256) {
        int row = it >> 3, c = it & 7;
        uint32_t soff = SWZ128(row * 128 + c * 16);
        *(float4*)(sQh + soff) = *(const float4*)(qhb + (size_t)row * DMODEL + c * 8);
    }

    auto cpa_kv = [&](int j, int s) {
        const int k0 = j * 64;
        const uint32_t st = uKV + s * KV_STAGE;
#pragma unroll
        for (int i = 0; i < 2; i++) {
            int it = tid + i * 256;
            int row = it >> 3, c = it & 7;
            uint32_t soff = SWZ128(row * 128 + c * 16);
            CP_ASYNC16(st + 0 * AK_B + soff, khb + (size_t)(k0 + row) * DMODEL + c * 8);
            CP_ASYNC16(st + 1 * AK_B + soff, vhb + (size_t)row * SEQ + k0 + c * 8);
        }
    };

    float O[8][4];
#pragma unroll
    for (int nt = 0; nt < 8; nt++)
#pragma unroll
        for (int e = 0; e < 4; e++) O[nt][e] = 0.f;
    float m0 = -1e30f, m1 = -1e30f, l0 = 0.f, l1 = 0.f;

    const int jmax = 2 * qb + 1;

    cpa_kv(0, 0); CP_COMMIT();

    for (int j = 0; j <= jmax; j++) {
        CP_WAIT(0);
        __syncthreads();
        if (j < jmax) { cpa_kv(j + 1, (j + 1) & 1); CP_COMMIT(); }

        const uint32_t uKh = uKV + (j & 1) * KV_STAGE;
        const uint32_t uVh = uKh + AK_B;
        const int k0 = j * 64;

        // ---- S = Qh·Kh  (log2-domain logits)
        float S[8][4];
#pragma unroll
        for (int nt = 0; nt < 8; nt++)
#pragma unroll
            for (int e = 0; e < 4; e++) S[nt][e] = 0.f;

#pragma unroll
        for (int kt = 0; kt < 4; kt++) {
            uint32_t aH[4];
            ldsm4(aH, uQh + rowbaseA + colA[kt]);
#pragma unroll
            for (int np = 0; np < 4; np++) {
                uint32_t bf[4];
                ldsm4(bf, uKh + rowbaseB + np * 2048 + colB[kt]);
                mma16816(S[2 * np + 0], aH, &bf[0]);
                mma16816(S[2 * np + 1], aH, &bf[2]);
            }
        }

        // ---- mask (diagonal tiles only)
        if (j >= 2 * qb) {
            const int qrow0 = q0loc + wid * 16 + g;
#pragma unroll
            for (int nt = 0; nt < 8; nt++) {
#pragma unroll
                for (int e = 0; e < 4; e++) {
                    int key = k0 + nt * 8 + t2 + (e & 1);
                    int qr  = qrow0 + ((e >> 1) * 8);
                    if (key > qr) S[nt][e] = -1e30f;
                }
            }
        }

        // ---- online softmax in log2 domain (rows g and g+8)
        float tm0 = -1e30f, tm1 = -1e30f;
#pragma unroll
        for (int nt = 0; nt < 8; nt++) {
            tm0 = fmaxf(tm0, fmaxf(S[nt][0], S[nt][1]));
            tm1 = fmaxf(tm1, fmaxf(S[nt][2], S[nt][3]));
        }
        tm0 = fmaxf(tm0, __shfl_xor_sync(0xffffffffu, tm0, 1));
        tm0 = fmaxf(tm0, __shfl_xor_sync(0xffffffffu, tm0, 2));
        tm1 = fmaxf(tm1, __shfl_xor_sync(0xffffffffu, tm1, 1));
        tm1 = fmaxf(tm1, __shfl_xor_sync(0xffffffffu, tm1, 2));
        float mn0 = fmaxf(m0, tm0), mn1 = fmaxf(m1, tm1);
        float al0 = exp2f(m0 - mn0), al1 = exp2f(m1 - mn1);
        float ls0 = 0.f, ls1 = 0.f;
#pragma unroll
        for (int nt = 0; nt < 8; nt++) {
            float p0 = exp2f(S[nt][0] - mn0);
            float p1 = exp2f(S[nt][1] - mn0);
            float p2 = exp2f(S[nt][2] - mn1);
            float p3 = exp2f(S[nt][3] - mn1);
            ls0 += p0 + p1; ls1 += p2 + p3;
            S[nt][0] = p0; S[nt][1] = p1; S[nt][2] = p2; S[nt][3] = p3;
        }
        ls0 += __shfl_xor_sync(0xffffffffu, ls0, 1);
        ls0 += __shfl_xor_sync(0xffffffffu, ls0, 2);
        ls1 += __shfl_xor_sync(0xffffffffu, ls1, 1);
        ls1 += __shfl_xor_sync(0xffffffffu, ls1, 2);
        l0 = l0 * al0 + ls0;  m0 = mn0;
        l1 = l1 * al1 + ls1;  m1 = mn1;
#pragma unroll
        for (int nt = 0; nt < 8; nt++) {
            O[nt][0] *= al0; O[nt][1] *= al0;
            O[nt][2] *= al1; O[nt][3] *= al1;
        }

        // ---- O += Ph·Vh  (P packed transiently per k16-chunk)
#pragma unroll
        for (int kc = 0; kc < 4; kc++) {
            uint32_t pH[4];
            pH[0] = pack_h2(S[2 * kc][0],     S[2 * kc][1]);
            pH[1] = pack_h2(S[2 * kc][2],     S[2 * kc][3]);
            pH[2] = pack_h2(S[2 * kc + 1][0], S[2 * kc + 1][1]);
            pH[3] = pack_h2(S[2 * kc + 1][2], S[2 * kc + 1][3]);
#pragma unroll
            for (int np = 0; np < 4; np++) {
                uint32_t vf[4];
                ldsm4(vf, uVh + rowbaseB + np * 2048 + colB[kc]);
                mma16816(O[2 * np + 0], pH, &vf[0]);
                mma16816(O[2 * np + 1], pH, &vf[2]);
            }
        }
    }

    // ---- epilogue: normalize, fp16, store (hi only)
    const float inv0 = 1.f / l0, inv1 = 1.f / l1;
    const int row0 = rowg + wid * 16 + g;
    const int row1 = row0 + 8;
#pragma unroll
    for (int nt = 0; nt < 8; nt++) {
        int col = h * HDIM + nt * 8 + t2;
        __half2 H0 = __floats2half2_rn(O[nt][0] * inv0, O[nt][1] * inv0);
        __half2 H1 = __floats2half2_rn(O[nt][2] * inv1, O[nt][3] * inv1);
        *(__half2*)(oh + (size_t)row0 * DMODEL + col) = H0;
        *(__half2*)(oh + (size_t)row1 * DMODEL + col) = H1;
    }
}

// ---------------------------------------------------------------------------
// Launch
// ---------------------------------------------------------------------------
extern "C" void kernel_launch(void* const* d_in, const int* in_sizes, int n_in,
                              void* d_out, int out_size)
{
    const float* x  = (const float*)d_in[0];
    const float* Wq = (const float*)d_in[1];
    const float* bq = (const float*)d_in[2];
    const float* Wk = (const float*)d_in[3];
    const float* bk = (const float*)d_in[4];
    const float* Wv = (const float*)d_in[5];
    const float* bv = (const float*)d_in[6];
    const float* Wo = (const float*)d_in[7];
    const float* bo = (const float*)d_in[8];
    float* out = (float*)d_out;

    __half *xh, *qh, *kh, *vth, *ath, *wh, *wl;
    cudaGetSymbolAddress((void**)&xh,  g_xh);
    cudaGetSymbolAddress((void**)&qh,  g_qh);
    cudaGetSymbolAddress((void**)&kh,  g_kh);
    cudaGetSymbolAddress((void**)&vth, g_vth);
    cudaGetSymbolAddress((void**)&ath, g_ath);
    cudaGetSymbolAddress((void**)&wh,  g_wh);
    cudaGetSymbolAddress((void**)&wl,  g_wl);

    const size_t WN = DMODEL * DMODEL;

    split_h<<<(MTOT * DMODEL / 4 + 255) / 256, 256>>>(x, xh, MTOT * DMODEL / 4);
    split_w4<<<dim3((WN / 4 + 255) / 256, 4), 256>>>(Wq, Wk, Wv, Wo, wh, wl);

    cudaFuncSetAttribute(gemm_hmma2, cudaFuncAttributeMaxDynamicSharedMemorySize, GEMM_SMEM);
    cudaFuncSetAttribute(attn_hmma, cudaFuncAttributeMaxDynamicSharedMemorySize, ATT_SMEM);

    GemmArgs3 qkv;
    qkv.g[0] = { xh, wh + 0 * WN, wl + 0 * WN, bq, nullptr, qh,  nullptr, 3, 1.0f };
    qkv.g[1] = { xh, wh + 1 * WN, wl + 1 * WN, bk, nullptr, kh,  nullptr, 3, K_FOLD };
    qkv.g[2] = { xh, wh + 2 * WN, wl + 2 * WN, bv, nullptr, vth, nullptr, 2, 1.0f };
    gemm_hmma2<<<dim3(DMODEL / 128, MTOT / 128, 3), 256, GEMM_SMEM>>>(qkv);

    attn_hmma<<<dim3(SEQ / 128, BATCH * NHEADS), 256, ATT_SMEM>>>(qh, kh, vth, ath);

    GemmArgs3 oproj;
    oproj.g[0] = { ath, wh + 3 * WN, wl + 3 * WN, bo, out, nullptr, nullptr, 0, 1.0f };
    oproj.g[1] = oproj.g[0];
    oproj.g[2] = oproj.g[0];
    gemm_hmma2<<<dim3(DMODEL / 128, MTOT / 128, 1), 256, GEMM_SMEM>>>(oproj);
}

// round 14
// speedup vs baseline: 1.5273x; 1.5273x over previous
#include <cuda_runtime.h>
#include <cuda_fp16.h>
#include <cstdint>
#include <math.h>

// Problem constants
#define BATCH   4
#define SEQ     2048
#define DMODEL  1024
#define NHEADS  16
#define HDIM    64
#define MTOT    (BATCH * SEQ)          // 8192 rows

// ---------------------------------------------------------------------------
// Scratch (static __device__ — no allocations allowed)
// ---------------------------------------------------------------------------
__device__ __half g_xh[MTOT * DMODEL];
__device__ __half g_qh[MTOT * DMODEL];
__device__ __half g_kh[MTOT * DMODEL];
__device__ __half g_vth[MTOT * DMODEL];   // [b*16+h][64 dims][2048 T]
__device__ __half g_ath[MTOT * DMODEL];
__device__ __half g_wh[4][DMODEL * DMODEL];
__device__ __half g_wl[4][DMODEL * DMODEL];

// ---------------------------------------------------------------------------
// mma.sync / ldmatrix / cp.async helpers (portable PTX, valid on plain sm_103)
// ---------------------------------------------------------------------------
__device__ __forceinline__ uint32_t smem_to_u32(const void* p) {
    uint32_t a;
    asm("{ .reg .u64 t; cvta.to.shared.u64 t, %1; cvt.u32.u64 %0, t; }" : "=r"(a) : "l"(p));
    return a;
}
__device__ __forceinline__ void ldsm4(uint32_t* d, uint32_t addr) {
    asm volatile("ldmatrix.sync.aligned.m8n8.x4.shared.b16 {%0,%1,%2,%3}, [%4];"
                 : "=r"(d[0]), "=r"(d[1]), "=r"(d[2]), "=r"(d[3]) : "r"(addr));
}
__device__ __forceinline__ void mma16816(float* c, const uint32_t* a, const uint32_t* b) {
    asm volatile("mma.sync.aligned.m16n8k16.row.col.f32.f16.f16.f32 "
                 "{%0,%1,%2,%3}, {%4,%5,%6,%7}, {%8,%9}, {%0,%1,%2,%3};"
                 : "+f"(c[0]), "+f"(c[1]), "+f"(c[2]), "+f"(c[3])
                 : "r"(a[0]), "r"(a[1]), "r"(a[2]), "r"(a[3]), "r"(b[0]), "r"(b[1]));
}
__device__ __forceinline__ uint32_t pack_h2(float a, float b) {
    __half2 t = __floats2half2_rn(a, b);
    return *reinterpret_cast<uint32_t*>(&t);
}
#define CP_ASYNC16(dst, src) \
    asm volatile("cp.async.cg.shared.global [%0], [%1], 16;" \
                 :: "r"(dst), "l"(__cvta_generic_to_global(src)) : "memory")
#define CP_COMMIT() asm volatile("cp.async.commit_group;" ::: "memory")
#define CP_WAIT(n)  asm volatile("cp.async.wait_group %0;" :: "n"(n) : "memory")

// SW128-style swizzle for 128B rows (all tiles)
#define SWZ128(o) ((o) ^ (((o) >> 3) & 0x70))

// scale (1/sqrt(64)) * log2(e) — folded into K at projection time
#define K_FOLD 0.18033688011112042f

// ---------------------------------------------------------------------------
// fp16 splits
// ---------------------------------------------------------------------------
__global__ void split_h(const float* __restrict__ in, __half* __restrict__ hi, int n4)
{
    int i = blockIdx.x * blockDim.x + threadIdx.x;
    if (i >= n4) return;
    float4 x = ((const float4*)in)[i];
    ((__half2*)hi)[i * 2 + 0] = __floats2half2_rn(x.x, x.y);
    ((__half2*)hi)[i * 2 + 1] = __floats2half2_rn(x.z, x.w);
}

__global__ void split_w4(const float* __restrict__ w0, const float* __restrict__ w1,
                         const float* __restrict__ w2, const float* __restrict__ w3,
                         __half* __restrict__ hi, __half* __restrict__ lo)
{
    const int n4 = DMODEL * DMODEL / 4;
    int i = blockIdx.x * blockDim.x + threadIdx.x;
    if (i >= n4) return;
    int z = blockIdx.y;
    const float* src = (z == 0) ? w0 : (z == 1) ? w1 : (z == 2) ? w2 : w3;
    size_t base = (size_t)z * (DMODEL * DMODEL / 2);   // in __half2 units
    float4 x = ((const float4*)src)[i];
    __half2 h0 = __floats2half2_rn(x.x, x.y);
    __half2 h1 = __floats2half2_rn(x.z, x.w);
    ((__half2*)hi)[base + i * 2 + 0] = h0;
    ((__half2*)hi)[base + i * 2 + 1] = h1;
    __half2 l0 = __floats2half2_rn(x.x - __half2float(h0.x), x.y - __half2float(h0.y));
    __half2 l1 = __floats2half2_rn(x.z - __half2float(h1.x), x.w - __half2float(h1.y));
    ((__half2*)lo)[base + i * 2 + 0] = l0;
    ((__half2*)lo)[base + i * 2 + 1] = l1;
}

// ---------------------------------------------------------------------------
// HMMA fp16 2-pass GEMM, BK=64. SW128 tiles throughout. (unchanged from R13)
// ---------------------------------------------------------------------------
#define BK 64
#define NCHUNK (DMODEL / BK)           // 16
#define TILE_BYTES (128 * 128)         // 16 KB
#define STAGE_BYTES (3 * TILE_BYTES)   // 48 KB
#define GEMM_SMEM (2 * STAGE_BYTES)    // 96 KB

struct GemmArgs {
    const __half* Ah;
    const __half* Bh;
    const __half* Bl;
    const float*  bias;
    float*        Cf;
    __half*       Ch;
    __half*       Cl;
    int           mode;     // 0 fp32; 1 hi/lo rows; 2 [b,h,d,T] (lo iff Cl); 3 hi rows
    float         cscale;   // output scale (K fold); 1.0 otherwise
};
struct GemmArgs3 { GemmArgs g[3]; };

__global__ __launch_bounds__(256, 2)
void gemm_hmma2(GemmArgs3 A3)
{
    const GemmArgs ga = A3.g[blockIdx.z];
    extern __shared__ __align__(16) char smem[];
    const uint32_t smem_u = smem_to_u32(smem);

    const int tid  = threadIdx.x;
    const int wid  = tid >> 5;
    const int lane = tid & 31;
    const int wm   = wid & 1;
    const int wn   = wid >> 1;
    const int m0 = blockIdx.y * 128;
    const int n0 = blockIdx.x * 128;

    const uint32_t mS = (uint32_t)(lane & 7) << 4;
    const int rowA_l = (lane & 7) + ((lane >> 3) & 1) * 8;
    const int chiA   = (lane >> 4) & 1;
    const int rbB_l  = (lane & 7) + ((lane >> 4) & 1) * 8;
    const int chiB   = (lane >> 3) & 1;
    const uint32_t rowbaseA = (uint32_t)(wm * 64 + rowA_l) * 128;
    const uint32_t rowbaseB = (uint32_t)(wn * 32 + rbB_l) * 128;
    uint32_t colA[4], colB[4];
#pragma unroll
    for (int kt = 0; kt < 4; kt++) {
        colA[kt] = ((uint32_t)((kt * 2 + chiA) * 16)) ^ mS;
        colB[kt] = ((uint32_t)((kt * 2 + chiB) * 16)) ^ mS;
    }

    float acc[4][4][4];
#pragma unroll
    for (int mt = 0; mt < 4; mt++)
#pragma unroll
        for (int nt = 0; nt < 4; nt++)
#pragma unroll
            for (int e = 0; e < 4; e++) acc[mt][nt][e] = 0.f;

    const __half* srcs[3] = { ga.Ah, ga.Bh, ga.Bl };

    auto cpa = [&](int c, int s) {
        const int k0 = c * BK;
        const uint32_t st = smem_u + s * STAGE_BYTES;
#pragma unroll
        for (int t = 0; t < 3; t++) {
            const __half* src = srcs[t];
            const int r0 = (t == 0) ? m0 : n0;
#pragma unroll
            for (int i = 0; i < 4; i++) {
                int fid = tid + i * 256;
                int row = fid >> 3, cc = fid & 7;
                uint32_t dst = st + t * TILE_BYTES + SWZ128(row * 128 + cc * 16);
                CP_ASYNC16(dst, src + (size_t)(r0 + row) * DMODEL + k0 + cc * 8);
            }
        }
    };

    auto mma_chunk = [&](int s) {
        const uint32_t sb = smem_u + s * STAGE_BYTES;
#pragma unroll
        for (int kt = 0; kt < 4; kt++) {
            uint32_t a[4][4];
#pragma unroll
            for (int mt = 0; mt < 4; mt++)
                ldsm4(a[mt], sb + rowbaseA + mt * 2048 + colA[kt]);
#pragma unroll
            for (int np = 0; np < 2; np++) {
                uint32_t bh[4], bl[4];
                ldsm4(bh, sb + TILE_BYTES + rowbaseB + np * 2048 + colB[kt]);
                ldsm4(bl, sb + 2 * TILE_BYTES + rowbaseB + np * 2048 + colB[kt]);
#pragma unroll
                for (int mt = 0; mt < 4; mt++) {
                    mma16816(acc[mt][2 * np + 0], a[mt], &bh[0]);
                    mma16816(acc[mt][2 * np + 1], a[mt], &bh[2]);
                    mma16816(acc[mt][2 * np + 0], a[mt], &bl[0]);
                    mma16816(acc[mt][2 * np + 1], a[mt], &bl[2]);
                }
            }
        }
    };

    cpa(0, 0); CP_COMMIT();
    for (int c = 0; c < NCHUNK; c++) {
        if (c + 1 < NCHUNK) {
            cpa(c + 1, (c + 1) & 1); CP_COMMIT();
            CP_WAIT(1);
        } else {
            CP_WAIT(0);
        }
        __syncthreads();
        mma_chunk(c & 1);
        __syncthreads();
    }

    // Epilogue
    const int g  = lane >> 2;
    const int t2 = (lane & 3) * 2;
#pragma unroll
    for (int mt = 0; mt < 4; mt++) {
#pragma unroll
        for (int nt = 0; nt < 4; nt++) {
            int row = m0 + wm * 64 + mt * 16 + g;
            int col = n0 + wn * 32 + nt * 8 + t2;
            float2 b = *(const float2*)&ga.bias[col];
            float v0 = (acc[mt][nt][0] + b.x) * ga.cscale;
            float v1 = (acc[mt][nt][1] + b.y) * ga.cscale;
            float v2 = (acc[mt][nt][2] + b.x) * ga.cscale;
            float v3 = (acc[mt][nt][3] + b.y) * ga.cscale;
            if (ga.mode == 0) {
                float2 o0 = { v0, v1 }, o1 = { v2, v3 };
                *(float2*)&ga.Cf[(size_t)row * DMODEL + col] = o0;
                *(float2*)&ga.Cf[(size_t)(row + 8) * DMODEL + col] = o1;
            } else if (ga.mode == 1) {
                __half2 H0 = __floats2half2_rn(v0, v1);
                __half2 H1 = __floats2half2_rn(v2, v3);
                *(__half2*)(ga.Ch + (size_t)row * DMODEL + col) = H0;
                *(__half2*)(ga.Ch + (size_t)(row + 8) * DMODEL + col) = H1;
                __half2 L0 = __floats2half2_rn(v0 - __half2float(H0.x), v1 - __half2float(H0.y));
                __half2 L1 = __floats2half2_rn(v2 - __half2float(H1.x), v3 - __half2float(H1.y));
                *(__half2*)(ga.Cl + (size_t)row * DMODEL + col) = L0;
                *(__half2*)(ga.Cl + (size_t)(row + 8) * DMODEL + col) = L1;
            } else if (ga.mode == 3) {
                __half2 H0 = __floats2half2_rn(v0, v1);
                __half2 H1 = __floats2half2_rn(v2, v3);
                *(__half2*)(ga.Ch + (size_t)row * DMODEL + col) = H0;
                *(__half2*)(ga.Ch + (size_t)(row + 8) * DMODEL + col) = H1;
            } else {
                // V transposed layout: idx = ((b*16+h)*64 + d)*2048 + t
#pragma unroll
                for (int e = 0; e < 4; e++) {
                    float v = (e == 0) ? v0 : (e == 1) ? v1 : (e == 2) ? v2 : v3;
                    int r = row + (e >= 2 ? 8 : 0);
                    int c = col + (e & 1);
                    int bb = r >> 11, t = r & 2047;
                    int hh = c >> 6, dl = c & 63;
                    size_t idx = ((size_t)((bb * 16 + hh) * 64 + dl)) * 2048 + t;
                    __half hv = __float2half_rn(v);
                    ga.Ch[idx] = hv;
                    if (ga.Cl) ga.Cl[idx] = __float2half_rn(v - __half2float(hv));
                }
            }
        }
    }
}

// ---------------------------------------------------------------------------
// HMMA pure-fp16 causal flash attention (log2-domain softmax).
// Q fragments hoisted into registers before the key loop (j-invariant).
// S = Qh·Kh (K carries scale*log2e) ; O = Ph·Vh ; fp32 accumulation.
// K/V hi-only double-buffered (2 x 16 KB). 48 KB smem, 2 CTAs/SM.
// ---------------------------------------------------------------------------
#define AQ_B (128 * 128)               // 16 KB Q tile
#define AK_B (64 * 128)                // 8 KB per K/V tile
#define KV_STAGE (2 * AK_B)            // 16 KB
#define ATT_SMEM (AQ_B + 2 * KV_STAGE) // 48 KB

__global__ __launch_bounds__(256, 2)
void attn_hmma(const __half* __restrict__ qh,
               const __half* __restrict__ kh,
               const __half* __restrict__ vth,
               __half* __restrict__ oh)
{
    extern __shared__ __align__(16) char smem[];
    const uint32_t smem_u = smem_to_u32(smem);
    char* sQh = smem;
    const uint32_t uQh = smem_u;
    const uint32_t uKV = uQh + AQ_B;

    const int tid  = threadIdx.x;
    const int wid  = tid >> 5;
    const int lane = tid & 31;
    const int g    = lane >> 2;
    const int t2   = (lane & 3) * 2;

    const int qb = (gridDim.x - 1) - blockIdx.x;   // heavy CTAs first
    const int bh = blockIdx.y;
    const int b  = bh >> 4;
    const int h  = bh & 15;

    const int q0loc  = qb * 128;
    const int rowg   = b * SEQ + q0loc;
    const __half* qhb = qh + (size_t)rowg * DMODEL + h * HDIM;
    const __half* khb = kh + (size_t)(b * SEQ) * DMODEL + h * HDIM;
    const __half* vhb = vth + (size_t)bh * 64 * SEQ;

    const uint32_t mS = (uint32_t)(lane & 7) << 4;
    const int rowA_l = (lane & 7) + ((lane >> 3) & 1) * 8;
    const int chiA   = (lane >> 4) & 1;
    const int rbB_l  = (lane & 7) + ((lane >> 4) & 1) * 8;
    const int chiB   = (lane >> 3) & 1;
    const uint32_t rowbaseA = (uint32_t)(wid * 16 + rowA_l) * 128;
    const uint32_t rowbaseB = (uint32_t)rbB_l * 128;
    uint32_t colA[4], colB[4];
#pragma unroll
    for (int kt = 0; kt < 4; kt++) {
        colA[kt] = ((uint32_t)((kt * 2 + chiA) * 16)) ^ mS;
        colB[kt] = ((uint32_t)((kt * 2 + chiB) * 16)) ^ mS;
    }

    // Load Q tile (hi only)
    for (int it = tid; it < 1024; it += 256) {
        int row = it >> 3, c = it & 7;
        uint32_t soff = SWZ128(row * 128 + c * 16);
        *(float4*)(sQh + soff) = *(const float4*)(qhb + (size_t)row * DMODEL + c * 8);
    }

    auto cpa_kv = [&](int j, int s) {
        const int k0 = j * 64;
        const uint32_t st = uKV + s * KV_STAGE;
#pragma unroll
        for (int i = 0; i < 2; i++) {
            int it = tid + i * 256;
            int row = it >> 3, c = it & 7;
            uint32_t soff = SWZ128(row * 128 + c * 16);
            CP_ASYNC16(st + 0 * AK_B + soff, khb + (size_t)(k0 + row) * DMODEL + c * 8);
            CP_ASYNC16(st + 1 * AK_B + soff, vhb + (size_t)row * SEQ + k0 + c * 8);
        }
    };

    cpa_kv(0, 0); CP_COMMIT();
    __syncthreads();   // Q tile visible to all threads

    // ---- Hoist Q fragments (j-invariant) into registers
    uint32_t aQ[4][4];
#pragma unroll
    for (int kt = 0; kt < 4; kt++)
        ldsm4(aQ[kt], uQh + rowbaseA + colA[kt]);

    float O[8][4];
#pragma unroll
    for (int nt = 0; nt < 8; nt++)
#pragma unroll
        for (int e = 0; e < 4; e++) O[nt][e] = 0.f;
    float m0 = -1e30f, m1 = -1e30f, l0 = 0.f, l1 = 0.f;

    const int jmax = 2 * qb + 1;

    for (int j = 0; j <= jmax; j++) {
        CP_WAIT(0);
        __syncthreads();
        if (j < jmax) { cpa_kv(j + 1, (j + 1) & 1); CP_COMMIT(); }

        const uint32_t uKh = uKV + (j & 1) * KV_STAGE;
        const uint32_t uVh = uKh + AK_B;
        const int k0 = j * 64;

        // ---- S = Qh·Kh  (log2-domain logits)
        float S[8][4];
#pragma unroll
        for (int nt = 0; nt < 8; nt++)
#pragma unroll
            for (int e = 0; e < 4; e++) S[nt][e] = 0.f;

#pragma unroll
        for (int kt = 0; kt < 4; kt++) {
#pragma unroll
            for (int np = 0; np < 4; np++) {
                uint32_t bf[4];
                ldsm4(bf, uKh + rowbaseB + np * 2048 + colB[kt]);
                mma16816(S[2 * np + 0], aQ[kt], &bf[0]);
                mma16816(S[2 * np + 1], aQ[kt], &bf[2]);
            }
        }

        // ---- mask (diagonal tiles only)
        if (j >= 2 * qb) {
            const int qrow0 = q0loc + wid * 16 + g;
#pragma unroll
            for (int nt = 0; nt < 8; nt++) {
#pragma unroll
                for (int e = 0; e < 4; e++) {
                    int key = k0 + nt * 8 + t2 + (e & 1);
                    int qr  = qrow0 + ((e >> 1) * 8);
                    if (key > qr) S[nt][e] = -1e30f;
                }
            }
        }

        // ---- online softmax in log2 domain (rows g and g+8)
        float tm0 = -1e30f, tm1 = -1e30f;
#pragma unroll
        for (int nt = 0; nt < 8; nt++) {
            tm0 = fmaxf(tm0, fmaxf(S[nt][0], S[nt][1]));
            tm1 = fmaxf(tm1, fmaxf(S[nt][2], S[nt][3]));
        }
        tm0 = fmaxf(tm0, __shfl_xor_sync(0xffffffffu, tm0, 1));
        tm0 = fmaxf(tm0, __shfl_xor_sync(0xffffffffu, tm0, 2));
        tm1 = fmaxf(tm1, __shfl_xor_sync(0xffffffffu, tm1, 1));
        tm1 = fmaxf(tm1, __shfl_xor_sync(0xffffffffu, tm1, 2));
        float mn0 = fmaxf(m0, tm0), mn1 = fmaxf(m1, tm1);
        float al0 = exp2f(m0 - mn0), al1 = exp2f(m1 - mn1);
        float ls0 = 0.f, ls1 = 0.f;
#pragma unroll
        for (int nt = 0; nt < 8; nt++) {
            float p0 = exp2f(S[nt][0] - mn0);
            float p1 = exp2f(S[nt][1] - mn0);
            float p2 = exp2f(S[nt][2] - mn1);
            float p3 = exp2f(S[nt][3] - mn1);
            ls0 += p0 + p1; ls1 += p2 + p3;
            S[nt][0] = p0; S[nt][1] = p1; S[nt][2] = p2; S[nt][3] = p3;
        }
        ls0 += __shfl_xor_sync(0xffffffffu, ls0, 1);
        ls0 += __shfl_xor_sync(0xffffffffu, ls0, 2);
        ls1 += __shfl_xor_sync(0xffffffffu, ls1, 1);
        ls1 += __shfl_xor_sync(0xffffffffu, ls1, 2);
        l0 = l0 * al0 + ls0;  m0 = mn0;
        l1 = l1 * al1 + ls1;  m1 = mn1;
#pragma unroll
        for (int nt = 0; nt < 8; nt++) {
            O[nt][0] *= al0; O[nt][1] *= al0;
            O[nt][2] *= al1; O[nt][3] *= al1;
        }

        // ---- O += Ph·Vh  (P packed transiently per k16-chunk)
#pragma unroll
        for (int kc = 0; kc < 4; kc++) {
            uint32_t pH[4];
            pH[0] = pack_h2(S[2 * kc][0],     S[2 * kc][1]);
            pH[1] = pack_h2(S[2 * kc][2],     S[2 * kc][3]);
            pH[2] = pack_h2(S[2 * kc + 1][0], S[2 * kc + 1][1]);
            pH[3] = pack_h2(S[2 * kc + 1][2], S[2 * kc + 1][3]);
#pragma unroll
            for (int np = 0; np < 4; np++) {
                uint32_t vf[4];
                ldsm4(vf, uVh + rowbaseB + np * 2048 + colB[kc]);
                mma16816(O[2 * np + 0], pH, &vf[0]);
                mma16816(O[2 * np + 1], pH, &vf[2]);
            }
        }
    }

    // ---- epilogue: normalize, fp16, store (hi only)
    const float inv0 = 1.f / l0, inv1 = 1.f / l1;
    const int row0 = rowg + wid * 16 + g;
    const int row1 = row0 + 8;
#pragma unroll
    for (int nt = 0; nt < 8; nt++) {
        int col = h * HDIM + nt * 8 + t2;
        __half2 H0 = __floats2half2_rn(O[nt][0] * inv0, O[nt][1] * inv0);
        __half2 H1 = __floats2half2_rn(O[nt][2] * inv1, O[nt][3] * inv1);
        *(__half2*)(oh + (size_t)row0 * DMODEL + col) = H0;
        *(__half2*)(oh + (size_t)row1 * DMODEL + col) = H1;
    }
}

// ---------------------------------------------------------------------------
// Launch
// ---------------------------------------------------------------------------
extern "C" void kernel_launch(void* const* d_in, const int* in_sizes, int n_in,
                              void* d_out, int out_size)
{
    const float* x  = (const float*)d_in[0];
    const float* Wq = (const float*)d_in[1];
    const float* bq = (const float*)d_in[2];
    const float* Wk = (const float*)d_in[3];
    const float* bk = (const float*)d_in[4];
    const float* Wv = (const float*)d_in[5];
    const float* bv = (const float*)d_in[6];
    const float* Wo = (const float*)d_in[7];
    const float* bo = (const float*)d_in[8];
    float* out = (float*)d_out;

    __half *xh, *qh, *kh, *vth, *ath, *wh, *wl;
    cudaGetSymbolAddress((void**)&xh,  g_xh);
    cudaGetSymbolAddress((void**)&qh,  g_qh);
    cudaGetSymbolAddress((void**)&kh,  g_kh);
    cudaGetSymbolAddress((void**)&vth, g_vth);
    cudaGetSymbolAddress((void**)&ath, g_ath);
    cudaGetSymbolAddress((void**)&wh,  g_wh);
    cudaGetSymbolAddress((void**)&wl,  g_wl);

    const size_t WN = DMODEL * DMODEL;

    split_h<<<(MTOT * DMODEL / 4 + 255) / 256, 256>>>(x, xh, MTOT * DMODEL / 4);
    split_w4<<<dim3((WN / 4 + 255) / 256, 4), 256>>>(Wq, Wk, Wv, Wo, wh, wl);

    cudaFuncSetAttribute(gemm_hmma2, cudaFuncAttributeMaxDynamicSharedMemorySize, GEMM_SMEM);
    cudaFuncSetAttribute(attn_hmma, cudaFuncAttributeMaxDynamicSharedMemorySize, ATT_SMEM);

    GemmArgs3 qkv;
    qkv.g[0] = { xh, wh + 0 * WN, wl + 0 * WN, bq, nullptr, qh,  nullptr, 3, 1.0f };
    qkv.g[1] = { xh, wh + 1 * WN, wl + 1 * WN, bk, nullptr, kh,  nullptr, 3, K_FOLD };
    qkv.g[2] = { xh, wh + 2 * WN, wl + 2 * WN, bv, nullptr, vth, nullptr, 2, 1.0f };
    gemm_hmma2<<<dim3(DMODEL / 128, MTOT / 128, 3), 256, GEMM_SMEM>>>(qkv);

    attn_hmma<<<dim3(SEQ / 128, BATCH * NHEADS), 256, ATT_SMEM>>>(qh, kh, vth, ath);

    GemmArgs3 oproj;
    oproj.g[0] = { ath, wh + 3 * WN, wl + 3 * WN, bo, out, nullptr, nullptr, 0, 1.0f };
    oproj.g[1] = oproj.g[0];
    oproj.g[2] = oproj.g[0];
    gemm_hmma2<<<dim3(DMODEL / 128, MTOT / 128, 1), 256, GEMM_SMEM>>>(oproj);
}

// round 15
// speedup vs baseline: 1.5523x; 1.0163x over previous
#include <cuda_runtime.h>
#include <cuda_fp16.h>
#include <cstdint>
#include <math.h>

// Problem constants
#define BATCH   4
#define SEQ     2048
#define DMODEL  1024
#define NHEADS  16
#define HDIM    64
#define MTOT    (BATCH * SEQ)          // 8192 rows

// ---------------------------------------------------------------------------
// Scratch (static __device__ — no allocations allowed)
// ---------------------------------------------------------------------------
__device__ __half g_xh[MTOT * DMODEL];
__device__ __half g_qh[MTOT * DMODEL];
__device__ __half g_kh[MTOT * DMODEL];
__device__ __half g_vth[MTOT * DMODEL];   // [b*16+h][64 dims][2048 T]
__device__ __half g_ath[MTOT * DMODEL];
__device__ __half g_wh[4][DMODEL * DMODEL];
__device__ __half g_wl[4][DMODEL * DMODEL];

// ---------------------------------------------------------------------------
// mma.sync / ldmatrix / cp.async helpers (portable PTX, valid on plain sm_103)
// ---------------------------------------------------------------------------
__device__ __forceinline__ uint32_t smem_to_u32(const void* p) {
    uint32_t a;
    asm("{ .reg .u64 t; cvta.to.shared.u64 t, %1; cvt.u32.u64 %0, t; }" : "=r"(a) : "l"(p));
    return a;
}
__device__ __forceinline__ void ldsm4(uint32_t* d, uint32_t addr) {
    asm volatile("ldmatrix.sync.aligned.m8n8.x4.shared.b16 {%0,%1,%2,%3}, [%4];"
                 : "=r"(d[0]), "=r"(d[1]), "=r"(d[2]), "=r"(d[3]) : "r"(addr));
}
__device__ __forceinline__ void mma16816(float* c, const uint32_t* a, const uint32_t* b) {
    asm volatile("mma.sync.aligned.m16n8k16.row.col.f32.f16.f16.f32 "
                 "{%0,%1,%2,%3}, {%4,%5,%6,%7}, {%8,%9}, {%0,%1,%2,%3};"
                 : "+f"(c[0]), "+f"(c[1]), "+f"(c[2]), "+f"(c[3])
                 : "r"(a[0]), "r"(a[1]), "r"(a[2]), "r"(a[3]), "r"(b[0]), "r"(b[1]));
}
__device__ __forceinline__ uint32_t pack_h2(float a, float b) {
    __half2 t = __floats2half2_rn(a, b);
    return *reinterpret_cast<uint32_t*>(&t);
}
#define CP_ASYNC16(dst, src) \
    asm volatile("cp.async.cg.shared.global [%0], [%1], 16;" \
                 :: "r"(dst), "l"(__cvta_generic_to_global(src)) : "memory")
#define CP_COMMIT() asm volatile("cp.async.commit_group;" ::: "memory")
#define CP_WAIT(n)  asm volatile("cp.async.wait_group %0;" :: "n"(n) : "memory")

// SW128-style swizzle for 128B rows (all tiles)
#define SWZ128(o) ((o) ^ (((o) >> 3) & 0x70))

// scale (1/sqrt(64)) * log2(e) — folded into K at projection time
#define K_FOLD 0.18033688011112042f

// ---------------------------------------------------------------------------
// fp16 splits
// ---------------------------------------------------------------------------
__global__ void split_h(const float* __restrict__ in, __half* __restrict__ hi, int n4)
{
    int i = blockIdx.x * blockDim.x + threadIdx.x;
    if (i >= n4) return;
    float4 x = ((const float4*)in)[i];
    ((__half2*)hi)[i * 2 + 0] = __floats2half2_rn(x.x, x.y);
    ((__half2*)hi)[i * 2 + 1] = __floats2half2_rn(x.z, x.w);
}

__global__ void split_w4(const float* __restrict__ w0, const float* __restrict__ w1,
                         const float* __restrict__ w2, const float* __restrict__ w3,
                         __half* __restrict__ hi, __half* __restrict__ lo)
{
    const int n4 = DMODEL * DMODEL / 4;
    int i = blockIdx.x * blockDim.x + threadIdx.x;
    if (i >= n4) return;
    int z = blockIdx.y;
    const float* src = (z == 0) ? w0 : (z == 1) ? w1 : (z == 2) ? w2 : w3;
    size_t base = (size_t)z * (DMODEL * DMODEL / 2);   // in __half2 units
    float4 x = ((const float4*)src)[i];
    __half2 h0 = __floats2half2_rn(x.x, x.y);
    __half2 h1 = __floats2half2_rn(x.z, x.w);
    ((__half2*)hi)[base + i * 2 + 0] = h0;
    ((__half2*)hi)[base + i * 2 + 1] = h1;
    __half2 l0 = __floats2half2_rn(x.x - __half2float(h0.x), x.y - __half2float(h0.y));
    __half2 l1 = __floats2half2_rn(x.z - __half2float(h1.x), x.w - __half2float(h1.y));
    ((__half2*)lo)[base + i * 2 + 0] = l0;
    ((__half2*)lo)[base + i * 2 + 1] = l1;
}

// ---------------------------------------------------------------------------
// HMMA fp16 2-pass GEMM, BK=64. SW128 tiles throughout.
// Mode-2 (V transposed) epilogue now goes through a smem transpose so the
// global stores are fully coalesced (was: 2-byte scattered stores).
// ---------------------------------------------------------------------------
#define BK 64
#define NCHUNK (DMODEL / BK)           // 16
#define TILE_BYTES (128 * 128)         // 16 KB
#define STAGE_BYTES (3 * TILE_BYTES)   // 48 KB
#define GEMM_SMEM (2 * STAGE_BYTES)    // 96 KB
#define TSTRIDE 136                    // halves per transposed row (272 B, 16B-aligned)

struct GemmArgs {
    const __half* Ah;
    const __half* Bh;
    const __half* Bl;
    const float*  bias;
    float*        Cf;
    __half*       Ch;
    __half*       Cl;
    int           mode;     // 0 fp32; 1 hi/lo rows; 2 [b,h,d,T] hi; 3 hi rows
    float         cscale;   // output scale (K fold); 1.0 otherwise
};
struct GemmArgs3 { GemmArgs g[3]; };

__global__ __launch_bounds__(256, 2)
void gemm_hmma2(GemmArgs3 A3)
{
    const GemmArgs ga = A3.g[blockIdx.z];
    extern __shared__ __align__(16) char smem[];
    const uint32_t smem_u = smem_to_u32(smem);

    const int tid  = threadIdx.x;
    const int wid  = tid >> 5;
    const int lane = tid & 31;
    const int wm   = wid & 1;
    const int wn   = wid >> 1;
    const int m0 = blockIdx.y * 128;
    const int n0 = blockIdx.x * 128;

    const uint32_t mS = (uint32_t)(lane & 7) << 4;
    const int rowA_l = (lane & 7) + ((lane >> 3) & 1) * 8;
    const int chiA   = (lane >> 4) & 1;
    const int rbB_l  = (lane & 7) + ((lane >> 4) & 1) * 8;
    const int chiB   = (lane >> 3) & 1;
    const uint32_t rowbaseA = (uint32_t)(wm * 64 + rowA_l) * 128;
    const uint32_t rowbaseB = (uint32_t)(wn * 32 + rbB_l) * 128;
    uint32_t colA[4], colB[4];
#pragma unroll
    for (int kt = 0; kt < 4; kt++) {
        colA[kt] = ((uint32_t)((kt * 2 + chiA) * 16)) ^ mS;
        colB[kt] = ((uint32_t)((kt * 2 + chiB) * 16)) ^ mS;
    }

    float acc[4][4][4];
#pragma unroll
    for (int mt = 0; mt < 4; mt++)
#pragma unroll
        for (int nt = 0; nt < 4; nt++)
#pragma unroll
            for (int e = 0; e < 4; e++) acc[mt][nt][e] = 0.f;

    const __half* srcs[3] = { ga.Ah, ga.Bh, ga.Bl };

    auto cpa = [&](int c, int s) {
        const int k0 = c * BK;
        const uint32_t st = smem_u + s * STAGE_BYTES;
#pragma unroll
        for (int t = 0; t < 3; t++) {
            const __half* src = srcs[t];
            const int r0 = (t == 0) ? m0 : n0;
#pragma unroll
            for (int i = 0; i < 4; i++) {
                int fid = tid + i * 256;
                int row = fid >> 3, cc = fid & 7;
                uint32_t dst = st + t * TILE_BYTES + SWZ128(row * 128 + cc * 16);
                CP_ASYNC16(dst, src + (size_t)(r0 + row) * DMODEL + k0 + cc * 8);
            }
        }
    };

    auto mma_chunk = [&](int s) {
        const uint32_t sb = smem_u + s * STAGE_BYTES;
#pragma unroll
        for (int kt = 0; kt < 4; kt++) {
            uint32_t a[4][4];
#pragma unroll
            for (int mt = 0; mt < 4; mt++)
                ldsm4(a[mt], sb + rowbaseA + mt * 2048 + colA[kt]);
#pragma unroll
            for (int np = 0; np < 2; np++) {
                uint32_t bh[4], bl[4];
                ldsm4(bh, sb + TILE_BYTES + rowbaseB + np * 2048 + colB[kt]);
                ldsm4(bl, sb + 2 * TILE_BYTES + rowbaseB + np * 2048 + colB[kt]);
#pragma unroll
                for (int mt = 0; mt < 4; mt++) {
                    mma16816(acc[mt][2 * np + 0], a[mt], &bh[0]);
                    mma16816(acc[mt][2 * np + 1], a[mt], &bh[2]);
                    mma16816(acc[mt][2 * np + 0], a[mt], &bl[0]);
                    mma16816(acc[mt][2 * np + 1], a[mt], &bl[2]);
                }
            }
        }
    };

    cpa(0, 0); CP_COMMIT();
    for (int c = 0; c < NCHUNK; c++) {
        if (c + 1 < NCHUNK) {
            cpa(c + 1, (c + 1) & 1); CP_COMMIT();
            CP_WAIT(1);
        } else {
            CP_WAIT(0);
        }
        __syncthreads();
        mma_chunk(c & 1);
        __syncthreads();
    }

    // Epilogue
    const int g  = lane >> 2;
    const int t2 = (lane & 3) * 2;

    if (ga.mode == 2) {
        // ---- V transposed epilogue via smem transpose (coalesced stores)
        __half* tb = (__half*)smem;   // [128 d][TSTRIDE halves]
#pragma unroll
        for (int mt = 0; mt < 4; mt++) {
#pragma unroll
            for (int nt = 0; nt < 4; nt++) {
                int rowL = wm * 64 + mt * 16 + g;          // local token
                int colL = wn * 32 + nt * 8 + t2;          // local dim
                float2 b = *(const float2*)&ga.bias[n0 + colL];
                tb[(colL + 0) * TSTRIDE + rowL]     = __float2half_rn(acc[mt][nt][0] + b.x);
                tb[(colL + 1) * TSTRIDE + rowL]     = __float2half_rn(acc[mt][nt][1] + b.y);
                tb[(colL + 0) * TSTRIDE + rowL + 8] = __float2half_rn(acc[mt][nt][2] + b.x);
                tb[(colL + 1) * TSTRIDE + rowL + 8] = __float2half_rn(acc[mt][nt][3] + b.y);
            }
        }
        __syncthreads();
        // copy out: thread -> d-row tid>>1, half-segment tid&1 (64 halves = 128B)
        const int r   = tid >> 1;
        const int seg = tid & 1;
        const int c   = n0 + r;
        const int bb  = m0 >> 11;
        const int t0  = m0 & 2047;
        const int hh  = c >> 6, dl = c & 63;
        size_t gbase = ((size_t)((bb * 16 + hh) * 64 + dl)) * 2048 + t0 + seg * 64;
        const float4* srcp = (const float4*)(tb + r * TSTRIDE + seg * 64);
        float4* dstp = (float4*)(ga.Ch + gbase);
#pragma unroll
        for (int i = 0; i < 8; i++) dstp[i] = srcp[i];
        return;
    }

#pragma unroll
    for (int mt = 0; mt < 4; mt++) {
#pragma unroll
        for (int nt = 0; nt < 4; nt++) {
            int row = m0 + wm * 64 + mt * 16 + g;
            int col = n0 + wn * 32 + nt * 8 + t2;
            float2 b = *(const float2*)&ga.bias[col];
            float v0 = (acc[mt][nt][0] + b.x) * ga.cscale;
            float v1 = (acc[mt][nt][1] + b.y) * ga.cscale;
            float v2 = (acc[mt][nt][2] + b.x) * ga.cscale;
            float v3 = (acc[mt][nt][3] + b.y) * ga.cscale;
            if (ga.mode == 0) {
                float2 o0 = { v0, v1 }, o1 = { v2, v3 };
                *(float2*)&ga.Cf[(size_t)row * DMODEL + col] = o0;
                *(float2*)&ga.Cf[(size_t)(row + 8) * DMODEL + col] = o1;
            } else if (ga.mode == 1) {
                __half2 H0 = __floats2half2_rn(v0, v1);
                __half2 H1 = __floats2half2_rn(v2, v3);
                *(__half2*)(ga.Ch + (size_t)row * DMODEL + col) = H0;
                *(__half2*)(ga.Ch + (size_t)(row + 8) * DMODEL + col) = H1;
                __half2 L0 = __floats2half2_rn(v0 - __half2float(H0.x), v1 - __half2float(H0.y));
                __half2 L1 = __floats2half2_rn(v2 - __half2float(H1.x), v3 - __half2float(H1.y));
                *(__half2*)(ga.Cl + (size_t)row * DMODEL + col) = L0;
                *(__half2*)(ga.Cl + (size_t)(row + 8) * DMODEL + col) = L1;
            } else {   // mode 3
                __half2 H0 = __floats2half2_rn(v0, v1);
                __half2 H1 = __floats2half2_rn(v2, v3);
                *(__half2*)(ga.Ch + (size_t)row * DMODEL + col) = H0;
                *(__half2*)(ga.Ch + (size_t)(row + 8) * DMODEL + col) = H1;
            }
        }
    }
}

// ---------------------------------------------------------------------------
// HMMA pure-fp16 causal flash attention (log2-domain softmax). Unchanged R14.
// Q fragments hoisted into registers before the key loop (j-invariant).
// S = Qh·Kh (K carries scale*log2e) ; O = Ph·Vh ; fp32 accumulation.
// ---------------------------------------------------------------------------
#define AQ_B (128 * 128)               // 16 KB Q tile
#define AK_B (64 * 128)                // 8 KB per K/V tile
#define KV_STAGE (2 * AK_B)            // 16 KB
#define ATT_SMEM (AQ_B + 2 * KV_STAGE) // 48 KB

__global__ __launch_bounds__(256, 2)
void attn_hmma(const __half* __restrict__ qh,
               const __half* __restrict__ kh,
               const __half* __restrict__ vth,
               __half* __restrict__ oh)
{
    extern __shared__ __align__(16) char smem[];
    const uint32_t smem_u = smem_to_u32(smem);
    char* sQh = smem;
    const uint32_t uQh = smem_u;
    const uint32_t uKV = uQh + AQ_B;

    const int tid  = threadIdx.x;
    const int wid  = tid >> 5;
    const int lane = tid & 31;
    const int g    = lane >> 2;
    const int t2   = (lane & 3) * 2;

    const int qb = (gridDim.x - 1) - blockIdx.x;   // heavy CTAs first
    const int bh = blockIdx.y;
    const int b  = bh >> 4;
    const int h  = bh & 15;

    const int q0loc  = qb * 128;
    const int rowg   = b * SEQ + q0loc;
    const __half* qhb = qh + (size_t)rowg * DMODEL + h * HDIM;
    const __half* khb = kh + (size_t)(b * SEQ) * DMODEL + h * HDIM;
    const __half* vhb = vth + (size_t)bh * 64 * SEQ;

    const uint32_t mS = (uint32_t)(lane & 7) << 4;
    const int rowA_l = (lane & 7) + ((lane >> 3) & 1) * 8;
    const int chiA   = (lane >> 4) & 1;
    const int rbB_l  = (lane & 7) + ((lane >> 4) & 1) * 8;
    const int chiB   = (lane >> 3) & 1;
    const uint32_t rowbaseA = (uint32_t)(wid * 16 + rowA_l) * 128;
    const uint32_t rowbaseB = (uint32_t)rbB_l * 128;
    uint32_t colA[4], colB[4];
#pragma unroll
    for (int kt = 0; kt < 4; kt++) {
        colA[kt] = ((uint32_t)((kt * 2 + chiA) * 16)) ^ mS;
        colB[kt] = ((uint32_t)((kt * 2 + chiB) * 16)) ^ mS;
    }

    // Load Q tile (hi only)
    for (int it = tid; it < 1024; it += 256) {
        int row = it >> 3, c = it & 7;
        uint32_t soff = SWZ128(row * 128 + c * 16);
        *(float4*)(sQh + soff) = *(const float4*)(qhb + (size_t)row * DMODEL + c * 8);
    }

    auto cpa_kv = [&](int j, int s) {
        const int k0 = j * 64;
        const uint32_t st = uKV + s * KV_STAGE;
#pragma unroll
        for (int i = 0; i < 2; i++) {
            int it = tid + i * 256;
            int row = it >> 3, c = it & 7;
            uint32_t soff = SWZ128(row * 128 + c * 16);
            CP_ASYNC16(st + 0 * AK_B + soff, khb + (size_t)(k0 + row) * DMODEL + c * 8);
            CP_ASYNC16(st + 1 * AK_B + soff, vhb + (size_t)row * SEQ + k0 + c * 8);
        }
    };

    cpa_kv(0, 0); CP_COMMIT();
    __syncthreads();   // Q tile visible to all threads

    // ---- Hoist Q fragments (j-invariant) into registers
    uint32_t aQ[4][4];
#pragma unroll
    for (int kt = 0; kt < 4; kt++)
        ldsm4(aQ[kt], uQh + rowbaseA + colA[kt]);

    float O[8][4];
#pragma unroll
    for (int nt = 0; nt < 8; nt++)
#pragma unroll
        for (int e = 0; e < 4; e++) O[nt][e] = 0.f;
    float m0 = -1e30f, m1 = -1e30f, l0 = 0.f, l1 = 0.f;

    const int jmax = 2 * qb + 1;

    for (int j = 0; j <= jmax; j++) {
        CP_WAIT(0);
        __syncthreads();
        if (j < jmax) { cpa_kv(j + 1, (j + 1) & 1); CP_COMMIT(); }

        const uint32_t uKh = uKV + (j & 1) * KV_STAGE;
        const uint32_t uVh = uKh + AK_B;
        const int k0 = j * 64;

        // ---- S = Qh·Kh  (log2-domain logits)
        float S[8][4];
#pragma unroll
        for (int nt = 0; nt < 8; nt++)
#pragma unroll
            for (int e = 0; e < 4; e++) S[nt][e] = 0.f;

#pragma unroll
        for (int kt = 0; kt < 4; kt++) {
#pragma unroll
            for (int np = 0; np < 4; np++) {
                uint32_t bf[4];
                ldsm4(bf, uKh + rowbaseB + np * 2048 + colB[kt]);
                mma16816(S[2 * np + 0], aQ[kt], &bf[0]);
                mma16816(S[2 * np + 1], aQ[kt], &bf[2]);
            }
        }

        // ---- mask (diagonal tiles only)
        if (j >= 2 * qb) {
            const int qrow0 = q0loc + wid * 16 + g;
#pragma unroll
            for (int nt = 0; nt < 8; nt++) {
#pragma unroll
                for (int e = 0; e < 4; e++) {
                    int key = k0 + nt * 8 + t2 + (e & 1);
                    int qr  = qrow0 + ((e >> 1) * 8);
                    if (key > qr) S[nt][e] = -1e30f;
                }
            }
        }

        // ---- online softmax in log2 domain (rows g and g+8)
        float tm0 = -1e30f, tm1 = -1e30f;
#pragma unroll
        for (int nt = 0; nt < 8; nt++) {
            tm0 = fmaxf(tm0, fmaxf(S[nt][0], S[nt][1]));
            tm1 = fmaxf(tm1, fmaxf(S[nt][2], S[nt][3]));
        }
        tm0 = fmaxf(tm0, __shfl_xor_sync(0xffffffffu, tm0, 1));
        tm0 = fmaxf(tm0, __shfl_xor_sync(0xffffffffu, tm0, 2));
        tm1 = fmaxf(tm1, __shfl_xor_sync(0xffffffffu, tm1, 1));
        tm1 = fmaxf(tm1, __shfl_xor_sync(0xffffffffu, tm1, 2));
        float mn0 = fmaxf(m0, tm0), mn1 = fmaxf(m1, tm1);
        float al0 = exp2f(m0 - mn0), al1 = exp2f(m1 - mn1);
        float ls0 = 0.f, ls1 = 0.f;
#pragma unroll
        for (int nt = 0; nt < 8; nt++) {
            float p0 = exp2f(S[nt][0] - mn0);
            float p1 = exp2f(S[nt][1] - mn0);
            float p2 = exp2f(S[nt][2] - mn1);
            float p3 = exp2f(S[nt][3] - mn1);
            ls0 += p0 + p1; ls1 += p2 + p3;
            S[nt][0] = p0; S[nt][1] = p1; S[nt][2] = p2; S[nt][3] = p3;
        }
        ls0 += __shfl_xor_sync(0xffffffffu, ls0, 1);
        ls0 += __shfl_xor_sync(0xffffffffu, ls0, 2);
        ls1 += __shfl_xor_sync(0xffffffffu, ls1, 1);
        ls1 += __shfl_xor_sync(0xffffffffu, ls1, 2);
        l0 = l0 * al0 + ls0;  m0 = mn0;
        l1 = l1 * al1 + ls1;  m1 = mn1;
#pragma unroll
        for (int nt = 0; nt < 8; nt++) {
            O[nt][0] *= al0; O[nt][1] *= al0;
            O[nt][2] *= al1; O[nt][3] *= al1;
        }

        // ---- O += Ph·Vh  (P packed transiently per k16-chunk)
#pragma unroll
        for (int kc = 0; kc < 4; kc++) {
            uint32_t pH[4];
            pH[0] = pack_h2(S[2 * kc][0],     S[2 * kc][1]);
            pH[1] = pack_h2(S[2 * kc][2],     S[2 * kc][3]);
            pH[2] = pack_h2(S[2 * kc + 1][0], S[2 * kc + 1][1]);
            pH[3] = pack_h2(S[2 * kc + 1][2], S[2 * kc + 1][3]);
#pragma unroll
            for (int np = 0; np < 4; np++) {
                uint32_t vf[4];
                ldsm4(vf, uVh + rowbaseB + np * 2048 + colB[kc]);
                mma16816(O[2 * np + 0], pH, &vf[0]);
                mma16816(O[2 * np + 1], pH, &vf[2]);
            }
        }
    }

    // ---- epilogue: normalize, fp16, store (hi only)
    const float inv0 = 1.f / l0, inv1 = 1.f / l1;
    const int row0 = rowg + wid * 16 + g;
    const int row1 = row0 + 8;
#pragma unroll
    for (int nt = 0; nt < 8; nt++) {
        int col = h * HDIM + nt * 8 + t2;
        __half2 H0 = __floats2half2_rn(O[nt][0] * inv0, O[nt][1] * inv0);
        __half2 H1 = __floats2half2_rn(O[nt][2] * inv1, O[nt][3] * inv1);
        *(__half2*)(oh + (size_t)row0 * DMODEL + col) = H0;
        *(__half2*)(oh + (size_t)row1 * DMODEL + col) = H1;
    }
}

// ---------------------------------------------------------------------------
// Launch
// ---------------------------------------------------------------------------
extern "C" void kernel_launch(void* const* d_in, const int* in_sizes, int n_in,
                              void* d_out, int out_size)
{
    const float* x  = (const float*)d_in[0];
    const float* Wq = (const float*)d_in[1];
    const float* bq = (const float*)d_in[2];
    const float* Wk = (const float*)d_in[3];
    const float* bk = (const float*)d_in[4];
    const float* Wv = (const float*)d_in[5];
    const float* bv = (const float*)d_in[6];
    const float* Wo = (const float*)d_in[7];
    const float* bo = (const float*)d_in[8];
    float* out = (float*)d_out;

    __half *xh, *qh, *kh, *vth, *ath, *wh, *wl;
    cudaGetSymbolAddress((void**)&xh,  g_xh);
    cudaGetSymbolAddress((void**)&qh,  g_qh);
    cudaGetSymbolAddress((void**)&kh,  g_kh);
    cudaGetSymbolAddress((void**)&vth, g_vth);
    cudaGetSymbolAddress((void**)&ath, g_ath);
    cudaGetSymbolAddress((void**)&wh,  g_wh);
    cudaGetSymbolAddress((void**)&wl,  g_wl);

    const size_t WN = DMODEL * DMODEL;

    split_h<<<(MTOT * DMODEL / 4 + 255) / 256, 256>>>(x, xh, MTOT * DMODEL / 4);
    split_w4<<<dim3((WN / 4 + 255) / 256, 4), 256>>>(Wq, Wk, Wv, Wo, wh, wl);

    cudaFuncSetAttribute(gemm_hmma2, cudaFuncAttributeMaxDynamicSharedMemorySize, GEMM_SMEM);
    cudaFuncSetAttribute(attn_hmma, cudaFuncAttributeMaxDynamicSharedMemorySize, ATT_SMEM);

    GemmArgs3 qkv;
    qkv.g[0] = { xh, wh + 0 * WN, wl + 0 * WN, bq, nullptr, qh,  nullptr, 3, 1.0f };
    qkv.g[1] = { xh, wh + 1 * WN, wl + 1 * WN, bk, nullptr, kh,  nullptr, 3, K_FOLD };
    qkv.g[2] = { xh, wh + 2 * WN, wl + 2 * WN, bv, nullptr, vth, nullptr, 2, 1.0f };
    gemm_hmma2<<<dim3(DMODEL / 128, MTOT / 128, 3), 256, GEMM_SMEM>>>(qkv);

    attn_hmma<<<dim3(SEQ / 128, BATCH * NHEADS), 256, ATT_SMEM>>>(qh, kh, vth, ath);

    GemmArgs3 oproj;
    oproj.g[0] = { ath, wh + 3 * WN, wl + 3 * WN, bo, out, nullptr, nullptr, 0, 1.0f };
    oproj.g[1] = oproj.g[0];
    oproj.g[2] = oproj.g[0];
    gemm_hmma2<<<dim3(DMODEL / 128, MTOT / 128, 1), 256, GEMM_SMEM>>>(oproj);
}

// round 16
// speedup vs baseline: 1.9187x; 1.2361x over previous
#include <cuda_runtime.h>
#include <cuda_fp16.h>
#include <cstdint>
#include <math.h>

// Problem constants
#define BATCH   4
#define SEQ     2048
#define DMODEL  1024
#define NHEADS  16
#define HDIM    64
#define MTOT    (BATCH * SEQ)          // 8192 rows

// ---------------------------------------------------------------------------
// Scratch (static __device__ — no allocations allowed)
// ---------------------------------------------------------------------------
__device__ __half g_xh[MTOT * DMODEL];
__device__ __half g_qh[MTOT * DMODEL];
__device__ __half g_kh[MTOT * DMODEL];
__device__ __half g_vth[MTOT * DMODEL];   // [b*16+h][64 dims][2048 T]
__device__ __half g_ath[MTOT * DMODEL];
__device__ __half g_wh[4][DMODEL * DMODEL];
__device__ __half g_wl[4][DMODEL * DMODEL];

// ---------------------------------------------------------------------------
// mma.sync / ldmatrix / cp.async helpers (portable PTX, valid on plain sm_103)
// ---------------------------------------------------------------------------
__device__ __forceinline__ uint32_t smem_to_u32(const void* p) {
    uint32_t a;
    asm("{ .reg .u64 t; cvta.to.shared.u64 t, %1; cvt.u32.u64 %0, t; }" : "=r"(a) : "l"(p));
    return a;
}
__device__ __forceinline__ void ldsm4(uint32_t* d, uint32_t addr) {
    asm volatile("ldmatrix.sync.aligned.m8n8.x4.shared.b16 {%0,%1,%2,%3}, [%4];"
                 : "=r"(d[0]), "=r"(d[1]), "=r"(d[2]), "=r"(d[3]) : "r"(addr));
}
__device__ __forceinline__ void mma16816(float* c, const uint32_t* a, const uint32_t* b) {
    asm volatile("mma.sync.aligned.m16n8k16.row.col.f32.f16.f16.f32 "
                 "{%0,%1,%2,%3}, {%4,%5,%6,%7}, {%8,%9}, {%0,%1,%2,%3};"
                 : "+f"(c[0]), "+f"(c[1]), "+f"(c[2]), "+f"(c[3])
                 : "r"(a[0]), "r"(a[1]), "r"(a[2]), "r"(a[3]), "r"(b[0]), "r"(b[1]));
}
__device__ __forceinline__ uint32_t pack_h2(float a, float b) {
    __half2 t = __floats2half2_rn(a, b);
    return *reinterpret_cast<uint32_t*>(&t);
}
#define CP_ASYNC16(dst, src) \
    asm volatile("cp.async.cg.shared.global [%0], [%1], 16;" \
                 :: "r"(dst), "l"(__cvta_generic_to_global(src)) : "memory")
#define CP_COMMIT() asm volatile("cp.async.commit_group;" ::: "memory")
#define CP_WAIT(n)  asm volatile("cp.async.wait_group %0;" :: "n"(n) : "memory")

// SW128-style swizzle for 128B rows (all tiles)
#define SWZ128(o) ((o) ^ (((o) >> 3) & 0x70))

// scale (1/sqrt(64)) * log2(e) — folded into K at projection time
#define K_FOLD 0.18033688011112042f

// ---------------------------------------------------------------------------
// fp16 splits
// ---------------------------------------------------------------------------
__global__ void split_h(const float* __restrict__ in, __half* __restrict__ hi, int n4)
{
    int i = blockIdx.x * blockDim.x + threadIdx.x;
    if (i >= n4) return;
    float4 x = ((const float4*)in)[i];
    ((__half2*)hi)[i * 2 + 0] = __floats2half2_rn(x.x, x.y);
    ((__half2*)hi)[i * 2 + 1] = __floats2half2_rn(x.z, x.w);
}

__global__ void split_w4(const float* __restrict__ w0, const float* __restrict__ w1,
                         const float* __restrict__ w2, const float* __restrict__ w3,
                         __half* __restrict__ hi, __half* __restrict__ lo)
{
    const int n4 = DMODEL * DMODEL / 4;
    int i = blockIdx.x * blockDim.x + threadIdx.x;
    if (i >= n4) return;
    int z = blockIdx.y;
    const float* src = (z == 0) ? w0 : (z == 1) ? w1 : (z == 2) ? w2 : w3;
    size_t base = (size_t)z * (DMODEL * DMODEL / 2);   // in __half2 units
    float4 x = ((const float4*)src)[i];
    __half2 h0 = __floats2half2_rn(x.x, x.y);
    __half2 h1 = __floats2half2_rn(x.z, x.w);
    ((__half2*)hi)[base + i * 2 + 0] = h0;
    ((__half2*)hi)[base + i * 2 + 1] = h1;
    __half2 l0 = __floats2half2_rn(x.x - __half2float(h0.x), x.y - __half2float(h0.y));
    __half2 l1 = __floats2half2_rn(x.z - __half2float(h1.x), x.w - __half2float(h1.y));
    ((__half2*)lo)[base + i * 2 + 0] = l0;
    ((__half2*)lo)[base + i * 2 + 1] = l1;
}

// ---------------------------------------------------------------------------
// HMMA fp16 GEMM, BK=64, SW128 tiles. npass=2: C = Ah·Wh + Ah·Wl (fp32 out);
// npass=1: C = Ah·Wh (fp16 outputs — W residual is below the output rounding).
// ---------------------------------------------------------------------------
#define BK 64
#define NCHUNK (DMODEL / BK)           // 16
#define TILE_BYTES (128 * 128)         // 16 KB
#define STAGE_BYTES (3 * TILE_BYTES)   // 48 KB
#define GEMM_SMEM (2 * STAGE_BYTES)    // 96 KB
#define TSTRIDE 136                    // halves per transposed row (272 B)

struct GemmArgs {
    const __half* Ah;
    const __half* Bh;
    const __half* Bl;
    const float*  bias;
    float*        Cf;
    __half*       Ch;
    __half*       Cl;
    int           mode;     // 0 fp32; 1 hi/lo rows; 2 [b,h,d,T] hi; 3 hi rows
    float         cscale;   // output scale (K fold); 1.0 otherwise
    int           npass;    // 1 or 2 B-passes
};
struct GemmArgs3 { GemmArgs g[3]; };

__global__ __launch_bounds__(256, 2)
void gemm_hmma2(GemmArgs3 A3)
{
    const GemmArgs ga = A3.g[blockIdx.z];
    const bool p2 = (ga.npass == 2);
    extern __shared__ __align__(16) char smem[];
    const uint32_t smem_u = smem_to_u32(smem);

    const int tid  = threadIdx.x;
    const int wid  = tid >> 5;
    const int lane = tid & 31;
    const int wm   = wid & 1;
    const int wn   = wid >> 1;
    const int m0 = blockIdx.y * 128;
    const int n0 = blockIdx.x * 128;

    const uint32_t mS = (uint32_t)(lane & 7) << 4;
    const int rowA_l = (lane & 7) + ((lane >> 3) & 1) * 8;
    const int chiA   = (lane >> 4) & 1;
    const int rbB_l  = (lane & 7) + ((lane >> 4) & 1) * 8;
    const int chiB   = (lane >> 3) & 1;
    const uint32_t rowbaseA = (uint32_t)(wm * 64 + rowA_l) * 128;
    const uint32_t rowbaseB = (uint32_t)(wn * 32 + rbB_l) * 128;
    uint32_t colA[4], colB[4];
#pragma unroll
    for (int kt = 0; kt < 4; kt++) {
        colA[kt] = ((uint32_t)((kt * 2 + chiA) * 16)) ^ mS;
        colB[kt] = ((uint32_t)((kt * 2 + chiB) * 16)) ^ mS;
    }

    float acc[4][4][4];
#pragma unroll
    for (int mt = 0; mt < 4; mt++)
#pragma unroll
        for (int nt = 0; nt < 4; nt++)
#pragma unroll
            for (int e = 0; e < 4; e++) acc[mt][nt][e] = 0.f;

    const __half* srcs[3] = { ga.Ah, ga.Bh, ga.Bl };
    const int ntiles = p2 ? 3 : 2;

    auto cpa = [&](int c, int s) {
        const int k0 = c * BK;
        const uint32_t st = smem_u + s * STAGE_BYTES;
        for (int t = 0; t < ntiles; t++) {
            const __half* src = srcs[t];
            const int r0 = (t == 0) ? m0 : n0;
#pragma unroll
            for (int i = 0; i < 4; i++) {
                int fid = tid + i * 256;
                int row = fid >> 3, cc = fid & 7;
                uint32_t dst = st + t * TILE_BYTES + SWZ128(row * 128 + cc * 16);
                CP_ASYNC16(dst, src + (size_t)(r0 + row) * DMODEL + k0 + cc * 8);
            }
        }
    };

    auto mma_chunk = [&](int s) {
        const uint32_t sb = smem_u + s * STAGE_BYTES;
#pragma unroll
        for (int kt = 0; kt < 4; kt++) {
            uint32_t a[4][4];
#pragma unroll
            for (int mt = 0; mt < 4; mt++)
                ldsm4(a[mt], sb + rowbaseA + mt * 2048 + colA[kt]);
#pragma unroll
            for (int np = 0; np < 2; np++) {
                uint32_t bh[4];
                ldsm4(bh, sb + TILE_BYTES + rowbaseB + np * 2048 + colB[kt]);
#pragma unroll
                for (int mt = 0; mt < 4; mt++) {
                    mma16816(acc[mt][2 * np + 0], a[mt], &bh[0]);
                    mma16816(acc[mt][2 * np + 1], a[mt], &bh[2]);
                }
                if (p2) {
                    uint32_t bl[4];
                    ldsm4(bl, sb + 2 * TILE_BYTES + rowbaseB + np * 2048 + colB[kt]);
#pragma unroll
                    for (int mt = 0; mt < 4; mt++) {
                        mma16816(acc[mt][2 * np + 0], a[mt], &bl[0]);
                        mma16816(acc[mt][2 * np + 1], a[mt], &bl[2]);
                    }
                }
            }
        }
    };

    cpa(0, 0); CP_COMMIT();
    for (int c = 0; c < NCHUNK; c++) {
        if (c + 1 < NCHUNK) {
            cpa(c + 1, (c + 1) & 1); CP_COMMIT();
            CP_WAIT(1);
        } else {
            CP_WAIT(0);
        }
        __syncthreads();
        mma_chunk(c & 1);
        __syncthreads();
    }

    // Epilogue
    const int g  = lane >> 2;
    const int t2 = (lane & 3) * 2;

    if (ga.mode == 2) {
        // ---- V transposed epilogue via smem transpose (coalesced stores)
        __half* tb = (__half*)smem;   // [128 d][TSTRIDE halves]
#pragma unroll
        for (int mt = 0; mt < 4; mt++) {
#pragma unroll
            for (int nt = 0; nt < 4; nt++) {
                int rowL = wm * 64 + mt * 16 + g;          // local token
                int colL = wn * 32 + nt * 8 + t2;          // local dim
                float2 b = *(const float2*)&ga.bias[n0 + colL];
                tb[(colL + 0) * TSTRIDE + rowL]     = __float2half_rn(acc[mt][nt][0] + b.x);
                tb[(colL + 1) * TSTRIDE + rowL]     = __float2half_rn(acc[mt][nt][1] + b.y);
                tb[(colL + 0) * TSTRIDE + rowL + 8] = __float2half_rn(acc[mt][nt][2] + b.x);
                tb[(colL + 1) * TSTRIDE + rowL + 8] = __float2half_rn(acc[mt][nt][3] + b.y);
            }
        }
        __syncthreads();
        const int r   = tid >> 1;
        const int seg = tid & 1;
        const int c   = n0 + r;
        const int bb  = m0 >> 11;
        const int t0  = m0 & 2047;
        const int hh  = c >> 6, dl = c & 63;
        size_t gbase = ((size_t)((bb * 16 + hh) * 64 + dl)) * 2048 + t0 + seg * 64;
        const float4* srcp = (const float4*)(tb + r * TSTRIDE + seg * 64);
        float4* dstp = (float4*)(ga.Ch + gbase);
#pragma unroll
        for (int i = 0; i < 8; i++) dstp[i] = srcp[i];
        return;
    }

#pragma unroll
    for (int mt = 0; mt < 4; mt++) {
#pragma unroll
        for (int nt = 0; nt < 4; nt++) {
            int row = m0 + wm * 64 + mt * 16 + g;
            int col = n0 + wn * 32 + nt * 8 + t2;
            float2 b = *(const float2*)&ga.bias[col];
            float v0 = (acc[mt][nt][0] + b.x) * ga.cscale;
            float v1 = (acc[mt][nt][1] + b.y) * ga.cscale;
            float v2 = (acc[mt][nt][2] + b.x) * ga.cscale;
            float v3 = (acc[mt][nt][3] + b.y) * ga.cscale;
            if (ga.mode == 0) {
                float2 o0 = { v0, v1 }, o1 = { v2, v3 };
                *(float2*)&ga.Cf[(size_t)row * DMODEL + col] = o0;
                *(float2*)&ga.Cf[(size_t)(row + 8) * DMODEL + col] = o1;
            } else if (ga.mode == 1) {
                __half2 H0 = __floats2half2_rn(v0, v1);
                __half2 H1 = __floats2half2_rn(v2, v3);
                *(__half2*)(ga.Ch + (size_t)row * DMODEL + col) = H0;
                *(__half2*)(ga.Ch + (size_t)(row + 8) * DMODEL + col) = H1;
                __half2 L0 = __floats2half2_rn(v0 - __half2float(H0.x), v1 - __half2float(H0.y));
                __half2 L1 = __floats2half2_rn(v2 - __half2float(H1.x), v3 - __half2float(H1.y));
                *(__half2*)(ga.Cl + (size_t)row * DMODEL + col) = L0;
                *(__half2*)(ga.Cl + (size_t)(row + 8) * DMODEL + col) = L1;
            } else {   // mode 3
                __half2 H0 = __floats2half2_rn(v0, v1);
                __half2 H1 = __floats2half2_rn(v2, v3);
                *(__half2*)(ga.Ch + (size_t)row * DMODEL + col) = H0;
                *(__half2*)(ga.Ch + (size_t)(row + 8) * DMODEL + col) = H1;
            }
        }
    }
}

// ---------------------------------------------------------------------------
// HMMA pure-fp16 causal flash attention (log2-domain softmax). Unchanged R15.
// ---------------------------------------------------------------------------
#define AQ_B (128 * 128)               // 16 KB Q tile
#define AK_B (64 * 128)                // 8 KB per K/V tile
#define KV_STAGE (2 * AK_B)            // 16 KB
#define ATT_SMEM (AQ_B + 2 * KV_STAGE) // 48 KB

__global__ __launch_bounds__(256, 2)
void attn_hmma(const __half* __restrict__ qh,
               const __half* __restrict__ kh,
               const __half* __restrict__ vth,
               __half* __restrict__ oh)
{
    extern __shared__ __align__(16) char smem[];
    const uint32_t smem_u = smem_to_u32(smem);
    char* sQh = smem;
    const uint32_t uQh = smem_u;
    const uint32_t uKV = uQh + AQ_B;

    const int tid  = threadIdx.x;
    const int wid  = tid >> 5;
    const int lane = tid & 31;
    const int g    = lane >> 2;
    const int t2   = (lane & 3) * 2;

    const int qb = (gridDim.x - 1) - blockIdx.x;   // heavy CTAs first
    const int bh = blockIdx.y;
    const int b  = bh >> 4;
    const int h  = bh & 15;

    const int q0loc  = qb * 128;
    const int rowg   = b * SEQ + q0loc;
    const __half* qhb = qh + (size_t)rowg * DMODEL + h * HDIM;
    const __half* khb = kh + (size_t)(b * SEQ) * DMODEL + h * HDIM;
    const __half* vhb = vth + (size_t)bh * 64 * SEQ;

    const uint32_t mS = (uint32_t)(lane & 7) << 4;
    const int rowA_l = (lane & 7) + ((lane >> 3) & 1) * 8;
    const int chiA   = (lane >> 4) & 1;
    const int rbB_l  = (lane & 7) + ((lane >> 4) & 1) * 8;
    const int chiB   = (lane >> 3) & 1;
    const uint32_t rowbaseA = (uint32_t)(wid * 16 + rowA_l) * 128;
    const uint32_t rowbaseB = (uint32_t)rbB_l * 128;
    uint32_t colA[4], colB[4];
#pragma unroll
    for (int kt = 0; kt < 4; kt++) {
        colA[kt] = ((uint32_t)((kt * 2 + chiA) * 16)) ^ mS;
        colB[kt] = ((uint32_t)((kt * 2 + chiB) * 16)) ^ mS;
    }

    // Load Q tile (hi only)
    for (int it = tid; it < 1024; it += 256) {
        int row = it >> 3, c = it & 7;
        uint32_t soff = SWZ128(row * 128 + c * 16);
        *(float4*)(sQh + soff) = *(const float4*)(qhb + (size_t)row * DMODEL + c * 8);
    }

    auto cpa_kv = [&](int j, int s) {
        const int k0 = j * 64;
        const uint32_t st = uKV + s * KV_STAGE;
#pragma unroll
        for (int i = 0; i < 2; i++) {
            int it = tid + i * 256;
            int row = it >> 3, c = it & 7;
            uint32_t soff = SWZ128(row * 128 + c * 16);
            CP_ASYNC16(st + 0 * AK_B + soff, khb + (size_t)(k0 + row) * DMODEL + c * 8);
            CP_ASYNC16(st + 1 * AK_B + soff, vhb + (size_t)row * SEQ + k0 + c * 8);
        }
    };

    cpa_kv(0, 0); CP_COMMIT();
    __syncthreads();   // Q tile visible to all threads

    // ---- Hoist Q fragments (j-invariant) into registers
    uint32_t aQ[4][4];
#pragma unroll
    for (int kt = 0; kt < 4; kt++)
        ldsm4(aQ[kt], uQh + rowbaseA + colA[kt]);

    float O[8][4];
#pragma unroll
    for (int nt = 0; nt < 8; nt++)
#pragma unroll
        for (int e = 0; e < 4; e++) O[nt][e] = 0.f;
    float m0 = -1e30f, m1 = -1e30f, l0 = 0.f, l1 = 0.f;

    const int jmax = 2 * qb + 1;

    for (int j = 0; j <= jmax; j++) {
        CP_WAIT(0);
        __syncthreads();
        if (j < jmax) { cpa_kv(j + 1, (j + 1) & 1); CP_COMMIT(); }

        const uint32_t uKh = uKV + (j & 1) * KV_STAGE;
        const uint32_t uVh = uKh + AK_B;
        const int k0 = j * 64;

        // ---- S = Qh·Kh  (log2-domain logits)
        float S[8][4];
#pragma unroll
        for (int nt = 0; nt < 8; nt++)
#pragma unroll
            for (int e = 0; e < 4; e++) S[nt][e] = 0.f;

#pragma unroll
        for (int kt = 0; kt < 4; kt++) {
#pragma unroll
            for (int np = 0; np < 4; np++) {
                uint32_t bf[4];
                ldsm4(bf, uKh + rowbaseB + np * 2048 + colB[kt]);
                mma16816(S[2 * np + 0], aQ[kt], &bf[0]);
                mma16816(S[2 * np + 1], aQ[kt], &bf[2]);
            }
        }

        // ---- mask (diagonal tiles only)
        if (j >= 2 * qb) {
            const int qrow0 = q0loc + wid * 16 + g;
#pragma unroll
            for (int nt = 0; nt < 8; nt++) {
#pragma unroll
                for (int e = 0; e < 4; e++) {
                    int key = k0 + nt * 8 + t2 + (e & 1);
                    int qr  = qrow0 + ((e >> 1) * 8);
                    if (key > qr) S[nt][e] = -1e30f;
                }
            }
        }

        // ---- online softmax in log2 domain (rows g and g+8)
        float tm0 = -1e30f, tm1 = -1e30f;
#pragma unroll
        for (int nt = 0; nt < 8; nt++) {
            tm0 = fmaxf(tm0, fmaxf(S[nt][0], S[nt][1]));
            tm1 = fmaxf(tm1, fmaxf(S[nt][2], S[nt][3]));
        }
        tm0 = fmaxf(tm0, __shfl_xor_sync(0xffffffffu, tm0, 1));
        tm0 = fmaxf(tm0, __shfl_xor_sync(0xffffffffu, tm0, 2));
        tm1 = fmaxf(tm1, __shfl_xor_sync(0xffffffffu, tm1, 1));
        tm1 = fmaxf(tm1, __shfl_xor_sync(0xffffffffu, tm1, 2));
        float mn0 = fmaxf(m0, tm0), mn1 = fmaxf(m1, tm1);
        float al0 = exp2f(m0 - mn0), al1 = exp2f(m1 - mn1);
        float ls0 = 0.f, ls1 = 0.f;
#pragma unroll
        for (int nt = 0; nt < 8; nt++) {
            float p0 = exp2f(S[nt][0] - mn0);
            float p1 = exp2f(S[nt][1] - mn0);
            float p2 = exp2f(S[nt][2] - mn1);
            float p3 = exp2f(S[nt][3] - mn1);
            ls0 += p0 + p1; ls1 += p2 + p3;
            S[nt][0] = p0; S[nt][1] = p1; S[nt][2] = p2; S[nt][3] = p3;
        }
        ls0 += __shfl_xor_sync(0xffffffffu, ls0, 1);
        ls0 += __shfl_xor_sync(0xffffffffu, ls0, 2);
        ls1 += __shfl_xor_sync(0xffffffffu, ls1, 1);
        ls1 += __shfl_xor_sync(0xffffffffu, ls1, 2);
        l0 = l0 * al0 + ls0;  m0 = mn0;
        l1 = l1 * al1 + ls1;  m1 = mn1;
#pragma unroll
        for (int nt = 0; nt < 8; nt++) {
            O[nt][0] *= al0; O[nt][1] *= al0;
            O[nt][2] *= al1; O[nt][3] *= al1;
        }

        // ---- O += Ph·Vh  (P packed transiently per k16-chunk)
#pragma unroll
        for (int kc = 0; kc < 4; kc++) {
            uint32_t pH[4];
            pH[0] = pack_h2(S[2 * kc][0],     S[2 * kc][1]);
            pH[1] = pack_h2(S[2 * kc][2],     S[2 * kc][3]);
            pH[2] = pack_h2(S[2 * kc + 1][0], S[2 * kc + 1][1]);
            pH[3] = pack_h2(S[2 * kc + 1][2], S[2 * kc + 1][3]);
#pragma unroll
            for (int np = 0; np < 4; np++) {
                uint32_t vf[4];
                ldsm4(vf, uVh + rowbaseB + np * 2048 + colB[kc]);
                mma16816(O[2 * np + 0], pH, &vf[0]);
                mma16816(O[2 * np + 1], pH, &vf[2]);
            }
        }
    }

    // ---- epilogue: normalize, fp16, store (hi only)
    const float inv0 = 1.f / l0, inv1 = 1.f / l1;
    const int row0 = rowg + wid * 16 + g;
    const int row1 = row0 + 8;
#pragma unroll
    for (int nt = 0; nt < 8; nt++) {
        int col = h * HDIM + nt * 8 + t2;
        __half2 H0 = __floats2half2_rn(O[nt][0] * inv0, O[nt][1] * inv0);
        __half2 H1 = __floats2half2_rn(O[nt][2] * inv1, O[nt][3] * inv1);
        *(__half2*)(oh + (size_t)row0 * DMODEL + col) = H0;
        *(__half2*)(oh + (size_t)row1 * DMODEL + col) = H1;
    }
}

// ---------------------------------------------------------------------------
// Launch
// ---------------------------------------------------------------------------
extern "C" void kernel_launch(void* const* d_in, const int* in_sizes, int n_in,
                              void* d_out, int out_size)
{
    const float* x  = (const float*)d_in[0];
    const float* Wq = (const float*)d_in[1];
    const float* bq = (const float*)d_in[2];
    const float* Wk = (const float*)d_in[3];
    const float* bk = (const float*)d_in[4];
    const float* Wv = (const float*)d_in[5];
    const float* bv = (const float*)d_in[6];
    const float* Wo = (const float*)d_in[7];
    const float* bo = (const float*)d_in[8];
    float* out = (float*)d_out;

    __half *xh, *qh, *kh, *vth, *ath, *wh, *wl;
    cudaGetSymbolAddress((void**)&xh,  g_xh);
    cudaGetSymbolAddress((void**)&qh,  g_qh);
    cudaGetSymbolAddress((void**)&kh,  g_kh);
    cudaGetSymbolAddress((void**)&vth, g_vth);
    cudaGetSymbolAddress((void**)&ath, g_ath);
    cudaGetSymbolAddress((void**)&wh,  g_wh);
    cudaGetSymbolAddress((void**)&wl,  g_wl);

    const size_t WN = DMODEL * DMODEL;

    split_h<<<(MTOT * DMODEL / 4 + 255) / 256, 256>>>(x, xh, MTOT * DMODEL / 4);
    split_w4<<<dim3((WN / 4 + 255) / 256, 4), 256>>>(Wq, Wk, Wv, Wo, wh, wl);

    cudaFuncSetAttribute(gemm_hmma2, cudaFuncAttributeMaxDynamicSharedMemorySize, GEMM_SMEM);
    cudaFuncSetAttribute(attn_hmma, cudaFuncAttributeMaxDynamicSharedMemorySize, ATT_SMEM);

    GemmArgs3 qkv;
    qkv.g[0] = { xh, wh + 0 * WN, wl + 0 * WN, bq, nullptr, qh,  nullptr, 3, 1.0f,   1 };
    qkv.g[1] = { xh, wh + 1 * WN, wl + 1 * WN, bk, nullptr, kh,  nullptr, 3, K_FOLD, 1 };
    qkv.g[2] = { xh, wh + 2 * WN, wl + 2 * WN, bv, nullptr, vth, nullptr, 2, 1.0f,   1 };
    gemm_hmma2<<<dim3(DMODEL / 128, MTOT / 128, 3), 256, GEMM_SMEM>>>(qkv);

    attn_hmma<<<dim3(SEQ / 128, BATCH * NHEADS), 256, ATT_SMEM>>>(qh, kh, vth, ath);

    GemmArgs3 oproj;
    oproj.g[0] = { ath, wh + 3 * WN, wl + 3 * WN, bo, out, nullptr, nullptr, 0, 1.0f, 2 };
    oproj.g[1] = oproj.g[0];
    oproj.g[2] = oproj.g[0];
    gemm_hmma2<<<dim3(DMODEL / 128, MTOT / 128, 1), 256, GEMM_SMEM>>>(oproj);
}